// round 13
// baseline (speedup 1.0000x reference)
#include <cuda_runtime.h>
#include <cuda_bf16.h>
#include <cuda_fp16.h>
#include <math.h>
#include <stdint.h>

#define Bn     4
#define Cc     256
#define Hh     128
#define Ww     128
#define HWn    16384
#define HEADSn 8
#define HDn    32
#define LINn   512
#define HIDn   680
#define MHn    128
#define NSPLIT 8

#define CHW    ((long)Cc*HWn)          // 4194304
#define NIMG   ((long)Bn*Cc*HWn)       // 16777216

// ------------------------- scratch (static device memory) -------------------
__device__ int   g_idx [Bn*LINn];
__device__ float g_pp  [Bn*MHn];
__device__ float g_t1v [Bn*LINn];
__device__ float g_t2v [Bn*LINn];
__device__ float g_Weff[Bn*Cc*Cc];
__device__ float g_beff[Bn*Cc];
__device__ float g_qn  [Bn*Cc*HWn];           // raw shuffled feature (pre-LN)
__device__ float g_q   [Bn*Cc*HWn];
__device__ float g_k   [Bn*Cc*HWn];
__device__ float g_att [Bn*Cc*HWn];
__device__ __half g_t16[(long)Bn*2*HIDn*HWn]; // 178 MB (fp16 FFN intermediate)
__device__ float g_Spart [NSPLIT*Bn*HEADSn*HDn*HDn];
__device__ float g_nqpart[NSPLIT*Bn*Cc];
__device__ float g_nkpart[NSPLIT*Bn*Cc];
__device__ float g_opm [Bn*Cc];
__device__ float g_spm [Bn*Cc];
__device__ float g_probs[Bn*HEADSn*HDn*HDn];
__device__ float g_M   [Bn*Cc*Cc];
__device__ float g_Watt[Bn*Cc*Cc];

// bf16 hi/lo split buffers
__device__ __nv_bfloat16 g_img_h[NIMG],  g_img_l[NIMG];
__device__ __nv_bfloat16 g_qn_h [NIMG],  g_qn_l [NIMG];
__device__ __nv_bfloat16 g_kn_h [NIMG],  g_kn_l [NIMG];
__device__ __nv_bfloat16 g_xln_h[NIMG],  g_xln_l[NIMG];
__device__ __nv_bfloat16 g_g_h[(long)Bn*HIDn*HWn], g_g_l[(long)Bn*HIDn*HWn];
__device__ __nv_bfloat16 g_Weff_h[Bn*Cc*Cc], g_Weff_l[Bn*Cc*Cc];
__device__ __nv_bfloat16 g_Watt_h[Bn*Cc*Cc], g_Watt_l[Bn*Cc*Cc];
__device__ __nv_bfloat16 g_qw_h[Cc*Cc],  g_qw_l[Cc*Cc];
__device__ __nv_bfloat16 g_kw_h[Cc*Cc],  g_kw_l[Cc*Cc];
__device__ __nv_bfloat16 g_piw_h[2*HIDn*Cc], g_piw_l[2*HIDn*Cc];
__device__ __nv_bfloat16 g_pow_h[Cc*HIDn],   g_pow_l[Cc*HIDn];

// ------------------------- PTX helpers --------------------------------------
__device__ __forceinline__ uint32_t s2u32(const void* p){
    uint32_t r;
    asm("{.reg .u64 t; cvta.to.shared.u64 t, %1; cvt.u32.u64 %0, t;}"
        : "=r"(r) : "l"(p));
    return r;
}
__device__ __forceinline__ void ldsm_x4(uint32_t* r, uint32_t a){
    asm volatile("ldmatrix.sync.aligned.m8n8.x4.shared.b16 {%0,%1,%2,%3},[%4];"
        : "=r"(r[0]),"=r"(r[1]),"=r"(r[2]),"=r"(r[3]) : "r"(a));
}
__device__ __forceinline__ void ldsm_x4t(uint32_t* r, uint32_t a){
    asm volatile("ldmatrix.sync.aligned.m8n8.x4.trans.shared.b16 {%0,%1,%2,%3},[%4];"
        : "=r"(r[0]),"=r"(r[1]),"=r"(r[2]),"=r"(r[3]) : "r"(a));
}
__device__ __forceinline__ void mma16816(float* c, const uint32_t* a, const uint32_t* b){
    asm volatile("mma.sync.aligned.m16n8k16.row.col.f32.bf16.bf16.f32 "
        "{%0,%1,%2,%3},{%4,%5,%6,%7},{%8,%9},{%0,%1,%2,%3};"
        : "+f"(c[0]),"+f"(c[1]),"+f"(c[2]),"+f"(c[3])
        : "r"(a[0]),"r"(a[1]),"r"(a[2]),"r"(a[3]),"r"(b[0]),"r"(b[1]));
}
__device__ __forceinline__ void split1(float v, __nv_bfloat16& h, __nv_bfloat16& l){
    h = __float2bfloat16(v);
    l = __float2bfloat16(v - __bfloat162float(h));
}

// ------------------------- serial-order linear layers ------------------------
// EXACT serial accumulation order (rank-critical for the downstream argsort).
__global__ void k_lin(const float* __restrict__ W, const float* __restrict__ x,
                      const float* __restrict__ bias, float* __restrict__ y,
                      int Odim, int In)
{
    int b = blockIdx.y;
    int o = blockIdx.x*32 + threadIdx.x;
    if (o >= Odim) return;
    const float* xr = x + (long)b*In;
    const float* wr = W + (long)o*In;
    float a = bias[o];
#pragma unroll 8
    for (int i = 0; i < In; i++) a += xr[i]*wr[i];
    y[(long)b*Odim + o] = a;
}

// ------------------------- stable descending rank (== top_k indices) --------
__global__ void k_rank(const float* __restrict__ t2)
{
    int b = blockIdx.x, t = threadIdx.x;    // 512 threads
    __shared__ float s[LINn];
    s[t] = t2[b*LINn + t];
    __syncthreads();
    float v = s[t];
    int rank = 0;
    for (int i = 0; i < LINn; i++) {
        float u = s[i];
        rank += (u > v) || (u == v && i < t);
    }
    g_idx[b*LINn + rank] = t;
}

// ------------------------- effective shuffle weight -------------------------
__global__ void k_beff(const float* __restrict__ cow, const float* __restrict__ cob,
                       const float* __restrict__ c1b)
{
    int b = blockIdx.x, o = threadIdx.x;
    float a = cob[o];
    for (int j = 0; j < 2*Cc; j++) a += cow[o*2*Cc + j] * c1b[g_idx[b*LINn + j]];
    g_beff[b*Cc + o] = a;
}

__global__ void k_weff(const float* __restrict__ cow, const float* __restrict__ c1w)
{
    int b = blockIdx.z;
    int o = blockIdx.y*16 + threadIdx.y;
    int i = blockIdx.x*16 + threadIdx.x;
    __shared__ int sidx[2*Cc];
    int t = threadIdx.y*16 + threadIdx.x;
    sidx[t]       = g_idx[b*LINn + t];
    sidx[t + 256] = g_idx[b*LINn + t + 256];
    __syncthreads();
    float a = 0.f;
    for (int j = 0; j < 2*Cc; j++) a += cow[o*2*Cc + j] * c1w[sidx[j]*Cc + i];
    g_Weff[((long)b*Cc + o)*Cc + i] = a;
}

// ------------------------- elementwise fp32 -> (hi,lo) bf16 -----------------
__global__ void k_split(const float* __restrict__ s, __nv_bfloat16* __restrict__ h,
                        __nv_bfloat16* __restrict__ l, long n4)
{
    long i = (long)blockIdx.x*blockDim.x + threadIdx.x;
    if (i >= n4) return;
    float4 v = ((const float4*)s)[i];
    __nv_bfloat16 h0,h1,h2,h3,l0,l1,l2,l3;
    split1(v.x,h0,l0); split1(v.y,h1,l1); split1(v.z,h2,l2); split1(v.w,h3,l3);
    ((__nv_bfloat162*)h)[i*2]   = __nv_bfloat162(h0,h1);
    ((__nv_bfloat162*)h)[i*2+1] = __nv_bfloat162(h2,h3);
    ((__nv_bfloat162*)l)[i*2]   = __nv_bfloat162(l0,l1);
    ((__nv_bfloat162*)l)[i*2+1] = __nv_bfloat162(l2,l3);
}

// ------------------------- split-bf16 tensor-core GEMM ----------------------
// C = (Whi+Wlo)@(Xhi+Xlo) approx, fp32 accum. W:[M,K] bf16 row-major,
// X:[K,N] bf16 row-major. Output: fp32 C (+bias,+res) OR fp16 C16.
#define WP 40     // 32 + 8 pad (bf16)
#define XP 136    // 128 + 8 pad
__global__ __launch_bounds__(256)
void k_mma(const __nv_bfloat16* __restrict__ WhiG, const __nv_bfloat16* __restrict__ WloG,
           const __nv_bfloat16* __restrict__ XhiG, const __nv_bfloat16* __restrict__ XloG,
           float* __restrict__ Cg, __half* __restrict__ C16g,
           const float* __restrict__ biasg, const float* __restrict__ resg,
           int M, int K, int N, long sW, long sX, long sC, long sB, long sR)
{
    __shared__ __nv_bfloat16 sWh[128][WP], sWl[128][WP];
    __shared__ __nv_bfloat16 sXh[32][XP],  sXl[32][XP];

    int bz = blockIdx.z;
    const __nv_bfloat16* Wh = WhiG + (long)bz*sW;
    const __nv_bfloat16* Wl = WloG + (long)bz*sW;
    const __nv_bfloat16* Xh = XhiG + (long)bz*sX;
    const __nv_bfloat16* Xl = XloG + (long)bz*sX;
    float*  C   = Cg   ? Cg   + (long)bz*sC : nullptr;
    __half* C16 = C16g ? C16g + (long)bz*sC : nullptr;
    const float* bias = biasg ? biasg + (long)bz*sB : nullptr;
    const float* res  = resg  ? resg  + (long)bz*sR : nullptr;

    int m0 = blockIdx.y*128, n0 = blockIdx.x*128;
    int tid = threadIdx.x, lane = tid & 31, w = tid >> 5;
    int wr = w >> 2, wc = w & 3;      // warp tile: rows 64*wr.. , cols 32*wc..

    // staging thread mapping
    int wrow = tid >> 2;              // 0..63
    int wcol = (tid & 3) * 8;         // 0,8,16,24
    int xrow = tid >> 4;              // 0..15
    int xcol = (tid & 15) * 8;

    uint4 stWh[2], stWl[2], stXh[2], stXl[2];

    auto stage = [&](int kt){
        int k0 = kt*32;
#pragma unroll
        for (int p = 0; p < 2; p++) {
            int gm = m0 + wrow + p*64; if (gm > M-1) gm = M-1;
            int kk = k0 + wcol;
            if (kk + 8 <= K) {
                stWh[p] = *(const uint4*)(Wh + (long)gm*K + kk);
                stWl[p] = *(const uint4*)(Wl + (long)gm*K + kk);
            } else {
                stWh[p] = make_uint4(0,0,0,0);
                stWl[p] = make_uint4(0,0,0,0);
            }
            int gk = k0 + xrow + p*16;
            if (gk < K) {
                stXh[p] = *(const uint4*)(Xh + (long)gk*N + n0 + xcol);
                stXl[p] = *(const uint4*)(Xl + (long)gk*N + n0 + xcol);
            } else {
                stXh[p] = make_uint4(0,0,0,0);
                stXl[p] = make_uint4(0,0,0,0);
            }
        }
    };
    auto commit = [&](){
#pragma unroll
        for (int p = 0; p < 2; p++) {
            *(uint4*)&sWh[wrow + p*64][wcol] = stWh[p];
            *(uint4*)&sWl[wrow + p*64][wcol] = stWl[p];
            *(uint4*)&sXh[xrow + p*16][xcol] = stXh[p];
            *(uint4*)&sXl[xrow + p*16][xcol] = stXl[p];
        }
    };

    uint32_t aWh = s2u32(&sWh[0][0]), aWl = s2u32(&sWl[0][0]);
    uint32_t aXh = s2u32(&sXh[0][0]), aXl = s2u32(&sXl[0][0]);

    int arow = wr*64 + (lane & 15);          // + mt*16
    int acol = (lane >> 4) * 8;              // + ks
    int brow = ((lane >> 3) & 1)*8 + (lane & 7);   // + ks
    int bcol = wc*32 + (lane >> 4)*8;        // + np*16

    float acc[4][4][4];
#pragma unroll
    for (int i = 0; i < 4; i++)
#pragma unroll
        for (int j = 0; j < 4; j++)
#pragma unroll
            for (int q = 0; q < 4; q++) acc[i][j][q] = 0.f;

    int nt = (K + 31) >> 5;
    stage(0);
    for (int kt = 0; kt < nt; kt++) {
        __syncthreads();          // previous compute done
        commit();
        __syncthreads();
        if (kt + 1 < nt) stage(kt + 1);
#pragma unroll
        for (int ks = 0; ks < 32; ks += 16) {
            uint32_t bh[4][2], bl[4][2], tmp[4];
#pragma unroll
            for (int np = 0; np < 2; np++) {
                uint32_t off = (uint32_t)((ks + brow)*XP + bcol + np*16) * 2;
                ldsm_x4t(tmp, aXh + off);
                bh[np*2][0]=tmp[0]; bh[np*2][1]=tmp[1];
                bh[np*2+1][0]=tmp[2]; bh[np*2+1][1]=tmp[3];
                ldsm_x4t(tmp, aXl + off);
                bl[np*2][0]=tmp[0]; bl[np*2][1]=tmp[1];
                bl[np*2+1][0]=tmp[2]; bl[np*2+1][1]=tmp[3];
            }
#pragma unroll
            for (int mt = 0; mt < 4; mt++) {
                uint32_t ah[4], al[4];
                uint32_t off = (uint32_t)((arow + mt*16)*WP + ks + acol) * 2;
                ldsm_x4(ah, aWh + off);
                ldsm_x4(al, aWl + off);
#pragma unroll
                for (int ntl = 0; ntl < 4; ntl++) {
                    mma16816(acc[mt][ntl], ah, bh[ntl]);
                    mma16816(acc[mt][ntl], ah, bl[ntl]);
                    mma16816(acc[mt][ntl], al, bh[ntl]);
                }
            }
        }
    }

    int r = lane >> 2, cp = (lane & 3)*2;
#pragma unroll
    for (int mt = 0; mt < 4; mt++) {
        int mA = m0 + wr*64 + mt*16 + r;
        int mB = mA + 8;
#pragma unroll
        for (int ntl = 0; ntl < 4; ntl++) {
            int nn = n0 + wc*32 + ntl*8 + cp;
            if (mA < M) {
                float bv = bias ? bias[mA] : 0.f;
                float2 v = make_float2(acc[mt][ntl][0] + bv, acc[mt][ntl][1] + bv);
                if (res) { v.x += res[(long)mA*N + nn]; v.y += res[(long)mA*N + nn + 1]; }
                if (C16) *(__half2*)(C16 + (long)mA*N + nn) = __floats2half2_rn(v.x, v.y);
                else     *(float2*)(C + (long)mA*N + nn) = v;
            }
            if (mB < M) {
                float bv = bias ? bias[mB] : 0.f;
                float2 v = make_float2(acc[mt][ntl][2] + bv, acc[mt][ntl][3] + bv);
                if (res) { v.x += res[(long)mB*N + nn]; v.y += res[(long)mB*N + nn + 1]; }
                if (C16) *(__half2*)(C16 + (long)mB*N + nn) = __floats2half2_rn(v.x, v.y);
                else     *(float2*)(C + (long)mB*N + nn) = v;
            }
        }
    }
}

// ------------------------- scalar SGEMM (small Watt GEMM only) --------------
__global__ __launch_bounds__(256)
void k_gemm(const float* __restrict__ Wg, const float* __restrict__ Xg,
            float* __restrict__ Cg, int M, int K, int N, long sW, long sX, long sC)
{
    int bz = blockIdx.z;
    const float* W = Wg + (long)bz*sW;
    const float* X = Xg + (long)bz*sX;
    float*       C = Cg + (long)bz*sC;
    int m0 = blockIdx.y*128, n0 = blockIdx.x*128;
    __shared__ float Ws[8][128];
    __shared__ float Xs[8][128];
    int tid = threadIdx.x;
    int tx = tid & 15, ty = tid >> 4;
    float acc[8][8];
#pragma unroll
    for (int i = 0; i < 8; i++)
#pragma unroll
        for (int j = 0; j < 8; j++) acc[i][j] = 0.f;
    int wm = tid >> 1, wk = (tid & 1)*4;
    int xk = tid >> 5, xn = (tid & 31)*4;
    for (int k0 = 0; k0 < K; k0 += 8) {
        float4 wv = *(const float4*)(W + (long)(m0 + wm)*K + k0 + wk);
        Ws[wk+0][wm] = wv.x; Ws[wk+1][wm] = wv.y;
        Ws[wk+2][wm] = wv.z; Ws[wk+3][wm] = wv.w;
        *(float4*)&Xs[xk][xn] = *(const float4*)(X + (long)(k0 + xk)*N + n0 + xn);
        __syncthreads();
#pragma unroll
        for (int k = 0; k < 8; k++) {
            float a[8], bb[8];
#pragma unroll
            for (int i = 0; i < 4; i++) { a[i] = Ws[k][ty*4+i]; a[i+4] = Ws[k][64+ty*4+i]; }
#pragma unroll
            for (int j = 0; j < 4; j++) { bb[j] = Xs[k][tx*4+j]; bb[j+4] = Xs[k][64+tx*4+j]; }
#pragma unroll
            for (int i = 0; i < 8; i++)
#pragma unroll
                for (int j = 0; j < 8; j++) acc[i][j] += a[i]*bb[j];
        }
        __syncthreads();
    }
#pragma unroll
    for (int i = 0; i < 8; i++) {
        int m = m0 + ((i < 4) ? ty*4 + i : 64 + ty*4 + (i-4));
        float* crow = C + (long)m*N + n0;
        *(float4*)(crow + tx*4)      = make_float4(acc[i][0],acc[i][1],acc[i][2],acc[i][3]);
        *(float4*)(crow + 64 + tx*4) = make_float4(acc[i][4],acc[i][5],acc[i][6],acc[i][7]);
    }
}

// ------------------------- channel LayerNorm -> hi/lo bf16 ------------------
__global__ void k_ln(const float* __restrict__ src,
                     __nv_bfloat16* __restrict__ dh, __nv_bfloat16* __restrict__ dl,
                     const float* __restrict__ w, const float* __restrict__ bias)
{
    int b = blockIdx.y;
    int p4 = blockIdx.x*blockDim.x + threadIdx.x;   // float4 pixel group
    const float4* s = (const float4*)(src + (long)b*CHW) + p4;
    float4 sum = make_float4(0.f,0.f,0.f,0.f);
    float4 sq  = make_float4(0.f,0.f,0.f,0.f);
    for (int c = 0; c < Cc; c++) {
        float4 x = s[(long)c*(HWn/4)];
        sum.x += x.x; sum.y += x.y; sum.z += x.z; sum.w += x.w;
        sq.x += x.x*x.x; sq.y += x.y*x.y; sq.z += x.z*x.z; sq.w += x.w*x.w;
    }
    const float inv = 1.f/Cc;
    float4 mu = make_float4(sum.x*inv, sum.y*inv, sum.z*inv, sum.w*inv);
    float4 rs;
    rs.x = rsqrtf(sq.x*inv - mu.x*mu.x + 1e-5f);
    rs.y = rsqrtf(sq.y*inv - mu.y*mu.y + 1e-5f);
    rs.z = rsqrtf(sq.z*inv - mu.z*mu.z + 1e-5f);
    rs.w = rsqrtf(sq.w*inv - mu.w*mu.w + 1e-5f);
    long base = (long)b*CHW + (long)p4*4;
    for (int c = 0; c < Cc; c++) {
        float4 x = s[(long)c*(HWn/4)];
        float wc = w[c], bc = bias[c];
        float4 o;
        o.x = (x.x - mu.x)*rs.x*wc + bc;
        o.y = (x.y - mu.y)*rs.y*wc + bc;
        o.z = (x.z - mu.z)*rs.z*wc + bc;
        o.w = (x.w - mu.w)*rs.w*wc + bc;
        __nv_bfloat16 h0,h1,h2,h3,l0,l1,l2,l3;
        split1(o.x,h0,l0); split1(o.y,h1,l1); split1(o.z,h2,l2); split1(o.w,h3,l3);
        long idx2 = (base + (long)c*HWn) >> 1;
        ((__nv_bfloat162*)dh)[idx2]   = __nv_bfloat162(h0,h1);
        ((__nv_bfloat162*)dh)[idx2+1] = __nv_bfloat162(h2,h3);
        ((__nv_bfloat162*)dl)[idx2]   = __nv_bfloat162(l0,l1);
        ((__nv_bfloat162*)dl)[idx2+1] = __nv_bfloat162(l2,l3);
    }
}

// ------------------------- per-channel mean over HW (hi/lo input) -----------
__global__ void k_chmean(const __nv_bfloat16* __restrict__ hi,
                         const __nv_bfloat16* __restrict__ lo, float* __restrict__ dst)
{
    int b = blockIdx.y, c = blockIdx.x, t = threadIdx.x;
    const __nv_bfloat162* h2 = (const __nv_bfloat162*)(hi + ((long)b*Cc + c)*HWn);
    const __nv_bfloat162* l2 = (const __nv_bfloat162*)(lo + ((long)b*Cc + c)*HWn);
    float a = 0.f;
    for (int i = t; i < HWn/2; i += 256) {
        __nv_bfloat162 hv = h2[i], lv = l2[i];
        a += __bfloat162float(hv.x) + __bfloat162float(hv.y)
           + __bfloat162float(lv.x) + __bfloat162float(lv.y);
    }
    __shared__ float r[256];
    r[t] = a; __syncthreads();
    for (int o = 128; o > 0; o >>= 1) { if (t < o) r[t] += r[t+o]; __syncthreads(); }
    if (t == 0) dst[b*Cc + c] = r[0] * (1.f/HWn);
}

// ------------------------- per-head QK^T partial + row norms ----------------
__global__ void k_scores(const float* __restrict__ q, const float* __restrict__ k)
{
    int sp = blockIdx.x, h = blockIdx.y, b = blockIdx.z;
    int d = threadIdx.x, c = threadIdx.y;
    int tid = c*32 + d;
    const float* Q  = q + ((long)(b*Cc + h*HDn))*HWn;
    const float* Kp = k + ((long)(b*Cc + h*HDn))*HWn;
    __shared__ float qs[32][65], ks[32][65];
    const int chunk = HWn / NSPLIT;
    int n0 = sp*chunk;
    float acc = 0.f, accq = 0.f, acck = 0.f;
    int lr = tid >> 5;
    int lc = (tid & 31) * 2;
    for (int n = n0; n < n0 + chunk; n += 64) {
        float2 qv = *(const float2*)(Q  + (long)lr*HWn + n + lc);
        float2 kv = *(const float2*)(Kp + (long)lr*HWn + n + lc);
        __syncthreads();
        qs[lr][lc] = qv.x; qs[lr][lc+1] = qv.y;
        ks[lr][lc] = kv.x; ks[lr][lc+1] = kv.y;
        __syncthreads();
#pragma unroll 16
        for (int t = 0; t < 64; t++) acc += qs[c][t]*ks[d][t];
        if (d == 0) {
#pragma unroll 16
            for (int t = 0; t < 64; t++) { float v = qs[c][t]; accq += v*v; }
        }
        if (c == 0) {
#pragma unroll 16
            for (int t = 0; t < 64; t++) { float v = ks[d][t]; acck += v*v; }
        }
    }
    g_Spart[(((long)sp*Bn + b)*HEADSn + h)*1024 + tid] = acc;
    if (d == 0) g_nqpart[((long)sp*Bn + b)*Cc + h*HDn + c] = accq;
    if (c == 0) g_nkpart[((long)sp*Bn + b)*Cc + h*HDn + d] = acck;
}

// ------------------------- mask generator + softmax --------------------------
__global__ void k_masksm(const float* __restrict__ fp_w,  const float* __restrict__ fp_b,
                         const float* __restrict__ mg1_w, const float* __restrict__ mg1_b,
                         const float* __restrict__ mg2_w, const float* __restrict__ mg2_b,
                         const float* __restrict__ temp)
{
    int h = blockIdx.x, b = blockIdx.y;
    int t = threadIdx.x;                          // 1024 threads
    __shared__ float comb[64], fin[256], h1[128];
    if (t < 32)           comb[t] = g_opm[b*Cc + h*HDn + t];
    else if (t < 64)      comb[t] = g_spm[b*Cc + h*HDn + (t-32)];
    if (t >= 128 && t < 256) fin[t] = g_pp[b*MHn + (t-128)];
    __syncthreads();
    if (t < 128) {
        float a = fp_b[t];
#pragma unroll 8
        for (int i = 0; i < 64; i++) a += comb[i]*fp_w[t*64 + i];
        fin[t] = a;
    }
    __syncthreads();
    if (t < 128) {
        float a = mg1_b[t];
        for (int i = 0; i < 256; i++) a += fin[i]*mg1_w[t*256 + i];
        h1[t] = fmaxf(a, 0.f);
    }
    __syncthreads();
    float a = mg2_b[t];
    for (int i = 0; i < 128; i++) a += h1[i]*mg2_w[t*128 + i];
    float mg = 1.f / (1.f + expf(-a));

    int c = t >> 5, d = t & 31;
    float s = 0.f, nq = 0.f, nk = 0.f;
#pragma unroll
    for (int sp = 0; sp < NSPLIT; sp++) {
        s  += g_Spart[(((long)sp*Bn + b)*HEADSn + h)*1024 + t];
        nq += g_nqpart[((long)sp*Bn + b)*Cc + h*HDn + c];
        nk += g_nkpart[((long)sp*Bn + b)*Cc + h*HDn + d];
    }
    float val = s / (fmaxf(sqrtf(nq), 1e-12f) * fmaxf(sqrtf(nk), 1e-12f));
    val = val * temp[h] * mg;
    float m = val;
    for (int o = 16; o > 0; o >>= 1) m = fmaxf(m, __shfl_xor_sync(0xffffffffu, m, o));
    float e = expf(val - m);
    float ssum = e;
    for (int o = 16; o > 0; o >>= 1) ssum += __shfl_xor_sync(0xffffffffu, ssum, o);
    g_probs[((long)b*HEADSn + h)*1024 + t] = e / ssum;
}

// ------------------------- M = o_w · blockdiag(probs) -----------------------
__global__ void k_M(const float* __restrict__ o_w)
{
    int b = blockIdx.x, o = blockIdx.y;
    int col = threadIdx.x;
    __shared__ float ow[256];
    __shared__ float pr[HEADSn*HDn*HDn];
    ow[col] = o_w[o*Cc + col];
    for (int i = col; i < HEADSn*HDn*HDn; i += 256) pr[i] = g_probs[(long)b*HEADSn*HDn*HDn + i];
    __syncthreads();
    int h = col >> 5, d = col & 31;
    float a = 0.f;
#pragma unroll 8
    for (int c = 0; c < 32; c++) a += ow[h*HDn + c] * pr[h*1024 + c*32 + d];
    g_M[((long)b*Cc + o)*Cc + col] = a;
}

// ------------------------- depthwise 3x3 + exact gelu gate (fp16 in) --------
__global__ __launch_bounds__(256)
void k_dwgelu(const __half* __restrict__ tin, const float* __restrict__ dw)
{
    __shared__ float s1[10][36], s2[10][36];
    int zc = blockIdx.z;
    int b  = zc / HIDn;
    int c  = zc % HIDn;
    int x0 = blockIdx.x*32;
    int y0 = blockIdx.y*8;
    const __half* p1 = tin + ((long)b*2*HIDn + c)*HWn;
    const __half* p2 = p1 + (long)HIDn*HWn;

    for (int i = threadIdx.x; i < 340; i += 256) {
        int ry = i / 34, rx = i % 34;
        int yy = y0 + ry - 1, xx = x0 + rx - 1;
        bool ok = (yy >= 0) && (yy < Hh) && (xx >= 0) && (xx < Ww);
        long off = (long)yy*Ww + xx;
        s1[ry][rx] = ok ? __half2float(p1[off]) : 0.f;
        s2[ry][rx] = ok ? __half2float(p2[off]) : 0.f;
    }
    const float* w1 = dw + c*9;
    const float* w2 = dw + (c + HIDn)*9;
    float c1[9], c2[9];
#pragma unroll
    for (int i = 0; i < 9; i++) { c1[i] = w1[i]; c2[i] = w2[i]; }
    __syncthreads();

    int lx = threadIdx.x & 31, ly = threadIdx.x >> 5;
    float a1 = 0.f, a2 = 0.f;
#pragma unroll
    for (int ky = 0; ky < 3; ky++)
#pragma unroll
        for (int kx = 0; kx < 3; kx++) {
            a1 += s1[ly+ky][lx+kx]*c1[ky*3+kx];
            a2 += s2[ly+ky][lx+kx]*c2[ky*3+kx];
        }
    float g = 0.5f*a1*(1.f + erff(a1*0.70710678118654752f));
    float v = g * a2;
    long idx = ((long)b*HIDn + c)*HWn + (y0+ly)*Ww + (x0+lx);
    __nv_bfloat16 hh, ll;
    split1(v, hh, ll);
    g_g_h[idx] = hh;
    g_g_l[idx] = ll;
}

// ------------------------- vector copy (img2 passthrough) -------------------
__global__ void k_copy(const float* __restrict__ src, float* __restrict__ dst, long n4)
{
    long i = (long)blockIdx.x*blockDim.x + threadIdx.x;
    if (i < n4) ((float4*)dst)[i] = ((const float4*)src)[i];
}

// ----------------------------------------------------------------------------
extern "C" void kernel_launch(void* const* d_in, const int* in_sizes, int n_in,
                              void* d_out, int out_size)
{
    const float* img    = (const float*)d_in[0];
    const float* text   = (const float*)d_in[1];
    const float* lin1_w = (const float*)d_in[2];
    const float* lin1_b = (const float*)d_in[3];
    const float* lin3_w = (const float*)d_in[4];
    const float* lin3_b = (const float*)d_in[5];
    const float* c1w    = (const float*)d_in[6];
    const float* c1b    = (const float*)d_in[7];
    const float* cow    = (const float*)d_in[8];
    const float* cob    = (const float*)d_in[9];
    const float* n1w    = (const float*)d_in[10];
    const float* n1b    = (const float*)d_in[11];
    const float* n2w    = (const float*)d_in[12];
    const float* n2b    = (const float*)d_in[13];
    const float* n3w    = (const float*)d_in[14];
    const float* n3b    = (const float*)d_in[15];
    const float* q_w    = (const float*)d_in[16];
    const float* k_w    = (const float*)d_in[17];
    const float* v_w    = (const float*)d_in[18];
    const float* o_w    = (const float*)d_in[19];
    const float* temp   = (const float*)d_in[20];
    const float* fp_w   = (const float*)d_in[21];
    const float* fp_b   = (const float*)d_in[22];
    const float* pp_w   = (const float*)d_in[23];
    const float* pp_b   = (const float*)d_in[24];
    const float* mg1_w  = (const float*)d_in[25];
    const float* mg1_b  = (const float*)d_in[26];
    const float* mg2_w  = (const float*)d_in[27];
    const float* mg2_b  = (const float*)d_in[28];
    const float* pi_w   = (const float*)d_in[29];
    const float* dw_w   = (const float*)d_in[30];
    const float* po_w   = (const float*)d_in[31];
    float* out = (float*)d_out;

    float *p_Weff, *p_beff, *p_qn, *p_q, *p_k, *p_att, *p_opm, *p_spm, *p_M, *p_Watt;
    float *p_pp, *p_t1v, *p_t2v;
    __half *p_t16;
    cudaGetSymbolAddress((void**)&p_Weff, g_Weff);
    cudaGetSymbolAddress((void**)&p_beff, g_beff);
    cudaGetSymbolAddress((void**)&p_qn,   g_qn);
    cudaGetSymbolAddress((void**)&p_q,    g_q);
    cudaGetSymbolAddress((void**)&p_k,    g_k);
    cudaGetSymbolAddress((void**)&p_att,  g_att);
    cudaGetSymbolAddress((void**)&p_t16,  g_t16);
    cudaGetSymbolAddress((void**)&p_opm,  g_opm);
    cudaGetSymbolAddress((void**)&p_spm,  g_spm);
    cudaGetSymbolAddress((void**)&p_M,    g_M);
    cudaGetSymbolAddress((void**)&p_Watt, g_Watt);
    cudaGetSymbolAddress((void**)&p_pp,   g_pp);
    cudaGetSymbolAddress((void**)&p_t1v,  g_t1v);
    cudaGetSymbolAddress((void**)&p_t2v,  g_t2v);

    __nv_bfloat16 *imgh,*imgl,*qnh,*qnl,*knh,*knl,*xlh,*xll,*gh,*gl;
    __nv_bfloat16 *weh,*wel,*wah,*wal,*qwh,*qwl,*kwh,*kwl,*pih,*pil,*poh,*pol;
    cudaGetSymbolAddress((void**)&imgh, g_img_h); cudaGetSymbolAddress((void**)&imgl, g_img_l);
    cudaGetSymbolAddress((void**)&qnh,  g_qn_h);  cudaGetSymbolAddress((void**)&qnl,  g_qn_l);
    cudaGetSymbolAddress((void**)&knh,  g_kn_h);  cudaGetSymbolAddress((void**)&knl,  g_kn_l);
    cudaGetSymbolAddress((void**)&xlh,  g_xln_h); cudaGetSymbolAddress((void**)&xll,  g_xln_l);
    cudaGetSymbolAddress((void**)&gh,   g_g_h);   cudaGetSymbolAddress((void**)&gl,   g_g_l);
    cudaGetSymbolAddress((void**)&weh,  g_Weff_h);cudaGetSymbolAddress((void**)&wel,  g_Weff_l);
    cudaGetSymbolAddress((void**)&wah,  g_Watt_h);cudaGetSymbolAddress((void**)&wal,  g_Watt_l);
    cudaGetSymbolAddress((void**)&qwh,  g_qw_h);  cudaGetSymbolAddress((void**)&qwl,  g_qw_l);
    cudaGetSymbolAddress((void**)&kwh,  g_kw_h);  cudaGetSymbolAddress((void**)&kwl,  g_kw_l);
    cudaGetSymbolAddress((void**)&pih,  g_piw_h); cudaGetSymbolAddress((void**)&pil,  g_piw_l);
    cudaGetSymbolAddress((void**)&poh,  g_pow_h); cudaGetSymbolAddress((void**)&pol,  g_pow_l);

    // 0. input / static weight splits
    k_split<<<16384, 256>>>(img,  imgh, imgl, NIMG/4);
    k_split<<<64,    256>>>(q_w,  qwh,  qwl,  (long)Cc*Cc/4);
    k_split<<<64,    256>>>(k_w,  kwh,  kwl,  (long)Cc*Cc/4);
    k_split<<<340,   256>>>(pi_w, pih,  pil,  (long)2*HIDn*Cc/4);
    k_split<<<170,   256>>>(po_w, poh,  pol,  (long)Cc*HIDn/4);

    // 1. text MLP in exact serial order (rank-safe), spread across SMs
    k_lin<<<dim3(LINn/32, Bn), 32>>>(lin1_w, text,  lin1_b, p_t1v, LINn, LINn);
    k_lin<<<dim3(MHn/32,  Bn), 32>>>(pp_w,   text,  pp_b,   p_pp,  MHn,  LINn);
    k_lin<<<dim3(LINn/32, Bn), 32>>>(lin3_w, p_t1v, lin3_b, p_t2v, LINn, LINn);
    k_rank<<<Bn, LINn>>>(p_t2v);
    // 2. effective shuffle weight/bias
    k_beff<<<Bn, Cc>>>(cow, cob, c1b);
    k_weff<<<dim3(16,16,Bn), dim3(16,16)>>>(cow, c1w);
    k_split<<<256, 256>>>(p_Weff, weh, wel, (long)Bn*Cc*Cc/4);
    // 3. qn_raw = W_eff @ img + b_eff ; LN -> hi/lo splits
    k_mma<<<dim3(128,2,Bn), 256>>>(weh, wel, imgh, imgl, p_qn, nullptr, p_beff, nullptr,
                                   Cc, Cc, HWn, (long)Cc*Cc, CHW, CHW, Cc, 0);
    k_ln<<<dim3(16,Bn), 256>>>(p_qn, qnh, qnl, n1w, n1b);
    k_ln<<<dim3(16,Bn), 256>>>(img,  knh, knl, n2w, n2b);
    // 4. q = q_w@qn, k = k_w@kn (fp32 out for scores)
    k_mma<<<dim3(128,2,Bn), 256>>>(qwh, qwl, qnh, qnl, p_q, nullptr, nullptr, nullptr,
                                   Cc, Cc, HWn, 0, CHW, CHW, 0, 0);
    k_mma<<<dim3(128,2,Bn), 256>>>(kwh, kwl, knh, knl, p_k, nullptr, nullptr, nullptr,
                                   Cc, Cc, HWn, 0, CHW, CHW, 0, 0);
    // 5. channel means
    k_chmean<<<dim3(Cc,Bn), 256>>>(knh, knl, p_opm);
    k_chmean<<<dim3(Cc,Bn), 256>>>(qnh, qnl, p_spm);
    // 6. per-head scores partials + norms
    k_scores<<<dim3(NSPLIT, HEADSn, Bn), dim3(32,32)>>>(p_q, p_k);
    // 7. mask generator + softmax -> probs
    k_masksm<<<dim3(HEADSn, Bn), 1024>>>(fp_w, fp_b, mg1_w, mg1_b, mg2_w, mg2_b, temp);
    // 8. M = o_w · blockdiag(probs);  W_att = M @ v_w (small, scalar GEMM)
    k_M<<<dim3(Bn, Cc), 256>>>(o_w);
    k_gemm<<<dim3(2,2,Bn), 256>>>(p_M, v_w, p_Watt, Cc, Cc, Cc,
                                  (long)Cc*Cc, 0, (long)Cc*Cc);
    k_split<<<256, 256>>>(p_Watt, wah, wal, (long)Bn*Cc*Cc/4);
    // 9. att = W_att @ kn
    k_mma<<<dim3(128,2,Bn), 256>>>(wah, wal, knh, knl, p_att, nullptr, nullptr, nullptr,
                                   Cc, Cc, HWn, (long)Cc*Cc, CHW, CHW, 0, 0);
    // 10. FFN  (pi GEMM writes fp16 t-buffer — halves the biggest intermediate)
    k_ln<<<dim3(16,Bn), 256>>>(p_att, xlh, xll, n3w, n3b);
    k_mma<<<dim3(128,11,Bn), 256>>>(pih, pil, xlh, xll, nullptr, p_t16, nullptr, nullptr,
                                    2*HIDn, Cc, HWn, 0, CHW, (long)2*HIDn*HWn, 0, 0);
    k_dwgelu<<<dim3(4,16,Bn*HIDn), 256>>>(p_t16, dw_w);
    k_mma<<<dim3(128,2,Bn), 256>>>(poh, pol, gh, gl, out, nullptr, nullptr, p_att,
                                   Cc, HIDn, HWn, 0, (long)HIDn*HWn, CHW, 0, CHW);
    // 11. second tuple output: img2 passthrough
    if ((long)out_size >= 2*NIMG)
        k_copy<<<16384, 256>>>(img, out + NIMG, NIMG/4);
}

// round 14
// speedup vs baseline: 1.0694x; 1.0694x over previous
#include <cuda_runtime.h>
#include <cuda_bf16.h>
#include <math.h>
#include <stdint.h>

#define Bn     4
#define Cc     256
#define Hh     128
#define Ww     128
#define HWn    16384
#define HEADSn 8
#define HDn    32
#define LINn   512
#define HIDn   680
#define MHn    128
#define NSPLIT 8

#define CHW    ((long)Cc*HWn)          // 4194304
#define NIMG   ((long)Bn*Cc*HWn)       // 16777216

// ------------------------- scratch (static device memory) -------------------
__device__ int   g_idx [Bn*LINn];
__device__ float g_pp  [Bn*MHn];
__device__ float g_t1v [Bn*LINn];
__device__ float g_t2v [Bn*LINn];
__device__ float g_Weff[Bn*Cc*Cc];
__device__ float g_beff[Bn*Cc];
__device__ float g_qn  [Bn*Cc*HWn];           // raw shuffled feature (pre-LN)
__device__ float g_q   [Bn*Cc*HWn];
__device__ float g_k   [Bn*Cc*HWn];
__device__ float g_att [Bn*Cc*HWn];
__device__ float g_t   [Bn*2*HIDn*HWn];
__device__ float g_Spart [NSPLIT*Bn*HEADSn*HDn*HDn];
__device__ float g_nqpart[NSPLIT*Bn*Cc];
__device__ float g_nkpart[NSPLIT*Bn*Cc];
__device__ float g_opm [Bn*Cc];
__device__ float g_spm [Bn*Cc];
__device__ float g_probs[Bn*HEADSn*HDn*HDn];
__device__ float g_M   [Bn*Cc*Cc];
__device__ float g_Watt[Bn*Cc*Cc];

// bf16 hi/lo split buffers
__device__ __nv_bfloat16 g_img_h[NIMG],  g_img_l[NIMG];
__device__ __nv_bfloat16 g_qn_h [NIMG],  g_qn_l [NIMG];
__device__ __nv_bfloat16 g_kn_h [NIMG],  g_kn_l [NIMG];
__device__ __nv_bfloat16 g_xln_h[NIMG],  g_xln_l[NIMG];
__device__ __nv_bfloat16 g_g_h[(long)Bn*HIDn*HWn], g_g_l[(long)Bn*HIDn*HWn];
__device__ __nv_bfloat16 g_Weff_h[Bn*Cc*Cc], g_Weff_l[Bn*Cc*Cc];
__device__ __nv_bfloat16 g_Watt_h[Bn*Cc*Cc], g_Watt_l[Bn*Cc*Cc];
__device__ __nv_bfloat16 g_qw_h[Cc*Cc],  g_qw_l[Cc*Cc];
__device__ __nv_bfloat16 g_kw_h[Cc*Cc],  g_kw_l[Cc*Cc];
__device__ __nv_bfloat16 g_piw_h[2*HIDn*Cc], g_piw_l[2*HIDn*Cc];
__device__ __nv_bfloat16 g_pow_h[Cc*HIDn],   g_pow_l[Cc*HIDn];

// ------------------------- PTX helpers --------------------------------------
__device__ __forceinline__ uint32_t s2u32(const void* p){
    uint32_t r;
    asm("{.reg .u64 t; cvta.to.shared.u64 t, %1; cvt.u32.u64 %0, t;}"
        : "=r"(r) : "l"(p));
    return r;
}
__device__ __forceinline__ void ldsm_x4(uint32_t* r, uint32_t a){
    asm volatile("ldmatrix.sync.aligned.m8n8.x4.shared.b16 {%0,%1,%2,%3},[%4];"
        : "=r"(r[0]),"=r"(r[1]),"=r"(r[2]),"=r"(r[3]) : "r"(a));
}
__device__ __forceinline__ void ldsm_x4t(uint32_t* r, uint32_t a){
    asm volatile("ldmatrix.sync.aligned.m8n8.x4.trans.shared.b16 {%0,%1,%2,%3},[%4];"
        : "=r"(r[0]),"=r"(r[1]),"=r"(r[2]),"=r"(r[3]) : "r"(a));
}
__device__ __forceinline__ void mma16816(float* c, const uint32_t* a, const uint32_t* b){
    asm volatile("mma.sync.aligned.m16n8k16.row.col.f32.bf16.bf16.f32 "
        "{%0,%1,%2,%3},{%4,%5,%6,%7},{%8,%9},{%0,%1,%2,%3};"
        : "+f"(c[0]),"+f"(c[1]),"+f"(c[2]),"+f"(c[3])
        : "r"(a[0]),"r"(a[1]),"r"(a[2]),"r"(a[3]),"r"(b[0]),"r"(b[1]));
}
__device__ __forceinline__ void split1(float v, __nv_bfloat16& h, __nv_bfloat16& l){
    h = __float2bfloat16(v);
    l = __float2bfloat16(v - __bfloat162float(h));
}
__device__ __forceinline__ void cpa16(uint32_t s, const void* g, bool v){
    int sz = v ? 16 : 0;
    asm volatile("cp.async.cg.shared.global [%0], [%1], 16, %2;"
                 :: "r"(s), "l"(g), "r"(sz));
}
#define CP_COMMIT() asm volatile("cp.async.commit_group;")
#define CP_WAIT(n)  asm volatile("cp.async.wait_group %0;" :: "n"(n))

// ------------------------- serial-order linear layers ------------------------
// EXACT serial accumulation order (rank-critical for the downstream argsort).
__global__ void k_lin(const float* __restrict__ W, const float* __restrict__ x,
                      const float* __restrict__ bias, float* __restrict__ y,
                      int Odim, int In)
{
    int b = blockIdx.y;
    int o = blockIdx.x*32 + threadIdx.x;
    if (o >= Odim) return;
    const float* xr = x + (long)b*In;
    const float* wr = W + (long)o*In;
    float a = bias[o];
#pragma unroll 8
    for (int i = 0; i < In; i++) a += xr[i]*wr[i];
    y[(long)b*Odim + o] = a;
}

// ------------------------- stable descending rank (== top_k indices) --------
__global__ void k_rank(const float* __restrict__ t2)
{
    int b = blockIdx.x, t = threadIdx.x;    // 512 threads
    __shared__ float s[LINn];
    s[t] = t2[b*LINn + t];
    __syncthreads();
    float v = s[t];
    int rank = 0;
    for (int i = 0; i < LINn; i++) {
        float u = s[i];
        rank += (u > v) || (u == v && i < t);
    }
    g_idx[b*LINn + rank] = t;
}

// ------------------------- effective shuffle weight -------------------------
__global__ void k_beff(const float* __restrict__ cow, const float* __restrict__ cob,
                       const float* __restrict__ c1b)
{
    int b = blockIdx.x, o = threadIdx.x;
    float a = cob[o];
    for (int j = 0; j < 2*Cc; j++) a += cow[o*2*Cc + j] * c1b[g_idx[b*LINn + j]];
    g_beff[b*Cc + o] = a;
}

__global__ void k_weff(const float* __restrict__ cow, const float* __restrict__ c1w)
{
    int b = blockIdx.z;
    int o = blockIdx.y*16 + threadIdx.y;
    int i = blockIdx.x*16 + threadIdx.x;
    __shared__ int sidx[2*Cc];
    int t = threadIdx.y*16 + threadIdx.x;
    sidx[t]       = g_idx[b*LINn + t];
    sidx[t + 256] = g_idx[b*LINn + t + 256];
    __syncthreads();
    float a = 0.f;
    for (int j = 0; j < 2*Cc; j++) a += cow[o*2*Cc + j] * c1w[sidx[j]*Cc + i];
    g_Weff[((long)b*Cc + o)*Cc + i] = a;
}

// ------------------------- elementwise fp32 -> (hi,lo) bf16 -----------------
__global__ void k_split(const float* __restrict__ s, __nv_bfloat16* __restrict__ h,
                        __nv_bfloat16* __restrict__ l, long n4)
{
    long i = (long)blockIdx.x*blockDim.x + threadIdx.x;
    if (i >= n4) return;
    float4 v = ((const float4*)s)[i];
    __nv_bfloat16 h0,h1,h2,h3,l0,l1,l2,l3;
    split1(v.x,h0,l0); split1(v.y,h1,l1); split1(v.z,h2,l2); split1(v.w,h3,l3);
    ((__nv_bfloat162*)h)[i*2]   = __nv_bfloat162(h0,h1);
    ((__nv_bfloat162*)h)[i*2+1] = __nv_bfloat162(h2,h3);
    ((__nv_bfloat162*)l)[i*2]   = __nv_bfloat162(l0,l1);
    ((__nv_bfloat162*)l)[i*2+1] = __nv_bfloat162(l2,l3);
}

// ------------------------- split-bf16 tensor-core GEMM (cp.async DB) --------
// C = (Whi+Wlo)@(Xhi+Xlo), fp32 accum. W:[M,K] bf16 rm, X:[K,N] bf16 rm.
// dyn smem: W area [2 buf][2 hl][128][40], X area [2][2][32][136]
#define WP 40
#define XP 136
#define MMA_SMEM (2*2*128*WP*2 + 2*2*32*XP*2)   // 40960 + 34816 = 75776
__global__ __launch_bounds__(256, 2)
void k_mma(const __nv_bfloat16* __restrict__ WhiG, const __nv_bfloat16* __restrict__ WloG,
           const __nv_bfloat16* __restrict__ XhiG, const __nv_bfloat16* __restrict__ XloG,
           float* __restrict__ Cg, const float* __restrict__ biasg,
           const float* __restrict__ resg,
           int M, int K, int N, long sW, long sX, long sC, long sB, long sR)
{
    extern __shared__ __align__(16) unsigned char dyn[];
    uint32_t aW = s2u32(dyn);
    uint32_t aX = aW + 40960;
    // strides (bytes): W buf 20480, W hl 10240; X buf 17408, X hl 8704

    int bz = blockIdx.z;
    const __nv_bfloat16* Wh = WhiG + (long)bz*sW;
    const __nv_bfloat16* Wl = WloG + (long)bz*sW;
    const __nv_bfloat16* Xh = XhiG + (long)bz*sX;
    const __nv_bfloat16* Xl = XloG + (long)bz*sX;
    float* C = Cg + (long)bz*sC;
    const float* bias = biasg ? biasg + (long)bz*sB : nullptr;
    const float* res  = resg  ? resg  + (long)bz*sR : nullptr;

    int m0 = blockIdx.y*128, n0 = blockIdx.x*128;
    int tid = threadIdx.x, lane = tid & 31, w = tid >> 5;
    int wr = w >> 2, wc = w & 3;

    int wrow = tid >> 2;              // 0..63
    int wcol = (tid & 3) * 8;
    int xrow = tid >> 4;              // 0..15
    int xcol = (tid & 15) * 8;

    auto issue = [&](int kt, int buf){
        long k0 = (long)kt*32;
#pragma unroll
        for (int p = 0; p < 2; p++) {
            int gm = m0 + wrow + p*64; if (gm >= M) gm = M - 1;
            long kk = k0 + wcol;
            bool vw = (kk + 8 <= (long)K);
            long kwc = vw ? kk : 0;
            uint32_t dW = aW + buf*20480 + (wrow + p*64)*80 + wcol*2;
            cpa16(dW,          Wh + (long)gm*K + kwc, vw);
            cpa16(dW + 10240,  Wl + (long)gm*K + kwc, vw);
            long gk = k0 + xrow + p*16;
            bool vx = (gk < (long)K);
            long gkc = vx ? gk : 0;
            uint32_t dX = aX + buf*17408 + (xrow + p*16)*272 + xcol*2;
            cpa16(dX,         Xh + gkc*N + n0 + xcol, vx);
            cpa16(dX + 8704,  Xl + gkc*N + n0 + xcol, vx);
        }
        CP_COMMIT();
    };

    int arow = wr*64 + (lane & 15);
    int acol = (lane >> 4) * 8;
    int brow = ((lane >> 3) & 1)*8 + (lane & 7);
    int bcol = wc*32 + (lane >> 4)*8;

    float acc[4][4][4];
#pragma unroll
    for (int i = 0; i < 4; i++)
#pragma unroll
        for (int j = 0; j < 4; j++)
#pragma unroll
            for (int q = 0; q < 4; q++) acc[i][j][q] = 0.f;

    int nt = (K + 31) >> 5;
    issue(0, 0);
    for (int kt = 0; kt < nt; kt++) {
        int buf = kt & 1;
        if (kt + 1 < nt) { issue(kt + 1, buf ^ 1); CP_WAIT(1); }
        else             { CP_WAIT(0); }
        __syncthreads();
        uint32_t bWh = aW + buf*20480, bWl = bWh + 10240;
        uint32_t bXh = aX + buf*17408, bXl = bXh + 8704;
#pragma unroll
        for (int ks = 0; ks < 32; ks += 16) {
            uint32_t bh[4][2], bl[4][2], tmp[4];
#pragma unroll
            for (int np = 0; np < 2; np++) {
                uint32_t off = (uint32_t)((ks + brow)*272 + (bcol + np*16)*2);
                ldsm_x4t(tmp, bXh + off);
                bh[np*2][0]=tmp[0]; bh[np*2][1]=tmp[1];
                bh[np*2+1][0]=tmp[2]; bh[np*2+1][1]=tmp[3];
                ldsm_x4t(tmp, bXl + off);
                bl[np*2][0]=tmp[0]; bl[np*2][1]=tmp[1];
                bl[np*2+1][0]=tmp[2]; bl[np*2+1][1]=tmp[3];
            }
#pragma unroll
            for (int mt = 0; mt < 4; mt++) {
                uint32_t ah[4], al[4];
                uint32_t off = (uint32_t)((arow + mt*16)*80 + (ks + acol)*2);
                ldsm_x4(ah, bWh + off);
                ldsm_x4(al, bWl + off);
#pragma unroll
                for (int ntl = 0; ntl < 4; ntl++) {
                    mma16816(acc[mt][ntl], ah, bh[ntl]);
                    mma16816(acc[mt][ntl], ah, bl[ntl]);
                    mma16816(acc[mt][ntl], al, bh[ntl]);
                }
            }
        }
        __syncthreads();
    }

    int r = lane >> 2, cp = (lane & 3)*2;
#pragma unroll
    for (int mt = 0; mt < 4; mt++) {
        int mA = m0 + wr*64 + mt*16 + r;
        int mB = mA + 8;
#pragma unroll
        for (int ntl = 0; ntl < 4; ntl++) {
            int nn = n0 + wc*32 + ntl*8 + cp;
            if (mA < M) {
                float bv = bias ? bias[mA] : 0.f;
                float2 v = make_float2(acc[mt][ntl][0] + bv, acc[mt][ntl][1] + bv);
                if (res) { v.x += res[(long)mA*N + nn]; v.y += res[(long)mA*N + nn + 1]; }
                *(float2*)(C + (long)mA*N + nn) = v;
            }
            if (mB < M) {
                float bv = bias ? bias[mB] : 0.f;
                float2 v = make_float2(acc[mt][ntl][2] + bv, acc[mt][ntl][3] + bv);
                if (res) { v.x += res[(long)mB*N + nn]; v.y += res[(long)mB*N + nn + 1]; }
                *(float2*)(C + (long)mB*N + nn) = v;
            }
        }
    }
}

// ------------------------- scalar SGEMM (small Watt GEMM only) --------------
__global__ __launch_bounds__(256)
void k_gemm(const float* __restrict__ Wg, const float* __restrict__ Xg,
            float* __restrict__ Cg, int M, int K, int N, long sW, long sX, long sC)
{
    int bz = blockIdx.z;
    const float* W = Wg + (long)bz*sW;
    const float* X = Xg + (long)bz*sX;
    float*       C = Cg + (long)bz*sC;
    int m0 = blockIdx.y*128, n0 = blockIdx.x*128;
    __shared__ float Ws[8][128];
    __shared__ float Xs[8][128];
    int tid = threadIdx.x;
    int tx = tid & 15, ty = tid >> 4;
    float acc[8][8];
#pragma unroll
    for (int i = 0; i < 8; i++)
#pragma unroll
        for (int j = 0; j < 8; j++) acc[i][j] = 0.f;
    int wm = tid >> 1, wk = (tid & 1)*4;
    int xk = tid >> 5, xn = (tid & 31)*4;
    for (int k0 = 0; k0 < K; k0 += 8) {
        float4 wv = *(const float4*)(W + (long)(m0 + wm)*K + k0 + wk);
        Ws[wk+0][wm] = wv.x; Ws[wk+1][wm] = wv.y;
        Ws[wk+2][wm] = wv.z; Ws[wk+3][wm] = wv.w;
        *(float4*)&Xs[xk][xn] = *(const float4*)(X + (long)(k0 + xk)*N + n0 + xn);
        __syncthreads();
#pragma unroll
        for (int k = 0; k < 8; k++) {
            float a[8], bb[8];
#pragma unroll
            for (int i = 0; i < 4; i++) { a[i] = Ws[k][ty*4+i]; a[i+4] = Ws[k][64+ty*4+i]; }
#pragma unroll
            for (int j = 0; j < 4; j++) { bb[j] = Xs[k][tx*4+j]; bb[j+4] = Xs[k][64+tx*4+j]; }
#pragma unroll
            for (int i = 0; i < 8; i++)
#pragma unroll
                for (int j = 0; j < 8; j++) acc[i][j] += a[i]*bb[j];
        }
        __syncthreads();
    }
#pragma unroll
    for (int i = 0; i < 8; i++) {
        int m = m0 + ((i < 4) ? ty*4 + i : 64 + ty*4 + (i-4));
        float* crow = C + (long)m*N + n0;
        *(float4*)(crow + tx*4)      = make_float4(acc[i][0],acc[i][1],acc[i][2],acc[i][3]);
        *(float4*)(crow + 64 + tx*4) = make_float4(acc[i][4],acc[i][5],acc[i][6],acc[i][7]);
    }
}

// ------------------------- channel LayerNorm -> hi/lo bf16 ------------------
__global__ void k_ln(const float* __restrict__ src,
                     __nv_bfloat16* __restrict__ dh, __nv_bfloat16* __restrict__ dl,
                     const float* __restrict__ w, const float* __restrict__ bias)
{
    int b = blockIdx.y;
    int p4 = blockIdx.x*blockDim.x + threadIdx.x;   // float4 pixel group
    const float4* s = (const float4*)(src + (long)b*CHW) + p4;
    float4 sum = make_float4(0.f,0.f,0.f,0.f);
    float4 sq  = make_float4(0.f,0.f,0.f,0.f);
    for (int c = 0; c < Cc; c++) {
        float4 x = s[(long)c*(HWn/4)];
        sum.x += x.x; sum.y += x.y; sum.z += x.z; sum.w += x.w;
        sq.x += x.x*x.x; sq.y += x.y*x.y; sq.z += x.z*x.z; sq.w += x.w*x.w;
    }
    const float inv = 1.f/Cc;
    float4 mu = make_float4(sum.x*inv, sum.y*inv, sum.z*inv, sum.w*inv);
    float4 rs;
    rs.x = rsqrtf(sq.x*inv - mu.x*mu.x + 1e-5f);
    rs.y = rsqrtf(sq.y*inv - mu.y*mu.y + 1e-5f);
    rs.z = rsqrtf(sq.z*inv - mu.z*mu.z + 1e-5f);
    rs.w = rsqrtf(sq.w*inv - mu.w*mu.w + 1e-5f);
    long base = (long)b*CHW + (long)p4*4;
    for (int c = 0; c < Cc; c++) {
        float4 x = s[(long)c*(HWn/4)];
        float wc = w[c], bc = bias[c];
        float4 o;
        o.x = (x.x - mu.x)*rs.x*wc + bc;
        o.y = (x.y - mu.y)*rs.y*wc + bc;
        o.z = (x.z - mu.z)*rs.z*wc + bc;
        o.w = (x.w - mu.w)*rs.w*wc + bc;
        __nv_bfloat16 h0,h1,h2,h3,l0,l1,l2,l3;
        split1(o.x,h0,l0); split1(o.y,h1,l1); split1(o.z,h2,l2); split1(o.w,h3,l3);
        long idx2 = (base + (long)c*HWn) >> 1;
        ((__nv_bfloat162*)dh)[idx2]   = __nv_bfloat162(h0,h1);
        ((__nv_bfloat162*)dh)[idx2+1] = __nv_bfloat162(h2,h3);
        ((__nv_bfloat162*)dl)[idx2]   = __nv_bfloat162(l0,l1);
        ((__nv_bfloat162*)dl)[idx2+1] = __nv_bfloat162(l2,l3);
    }
}

// ------------------------- per-channel mean over HW (hi/lo input) -----------
__global__ void k_chmean(const __nv_bfloat16* __restrict__ hi,
                         const __nv_bfloat16* __restrict__ lo, float* __restrict__ dst)
{
    int b = blockIdx.y, c = blockIdx.x, t = threadIdx.x;
    const __nv_bfloat162* h2 = (const __nv_bfloat162*)(hi + ((long)b*Cc + c)*HWn);
    const __nv_bfloat162* l2 = (const __nv_bfloat162*)(lo + ((long)b*Cc + c)*HWn);
    float a = 0.f;
    for (int i = t; i < HWn/2; i += 256) {
        __nv_bfloat162 hv = h2[i], lv = l2[i];
        a += __bfloat162float(hv.x) + __bfloat162float(hv.y)
           + __bfloat162float(lv.x) + __bfloat162float(lv.y);
    }
    __shared__ float r[256];
    r[t] = a; __syncthreads();
    for (int o = 128; o > 0; o >>= 1) { if (t < o) r[t] += r[t+o]; __syncthreads(); }
    if (t == 0) dst[b*Cc + c] = r[0] * (1.f/HWn);
}

// ------------------------- per-head QK^T partial + row norms ----------------
__global__ void k_scores(const float* __restrict__ q, const float* __restrict__ k)
{
    int sp = blockIdx.x, h = blockIdx.y, b = blockIdx.z;
    int d = threadIdx.x, c = threadIdx.y;
    int tid = c*32 + d;
    const float* Q  = q + ((long)(b*Cc + h*HDn))*HWn;
    const float* Kp = k + ((long)(b*Cc + h*HDn))*HWn;
    __shared__ float qs[32][65], ks[32][65];
    const int chunk = HWn / NSPLIT;
    int n0 = sp*chunk;
    float acc = 0.f, accq = 0.f, acck = 0.f;
    int lr = tid >> 5;
    int lc = (tid & 31) * 2;
    for (int n = n0; n < n0 + chunk; n += 64) {
        float2 qv = *(const float2*)(Q  + (long)lr*HWn + n + lc);
        float2 kv = *(const float2*)(Kp + (long)lr*HWn + n + lc);
        __syncthreads();
        qs[lr][lc] = qv.x; qs[lr][lc+1] = qv.y;
        ks[lr][lc] = kv.x; ks[lr][lc+1] = kv.y;
        __syncthreads();
#pragma unroll 16
        for (int t = 0; t < 64; t++) acc += qs[c][t]*ks[d][t];
        if (d == 0) {
#pragma unroll 16
            for (int t = 0; t < 64; t++) { float v = qs[c][t]; accq += v*v; }
        }
        if (c == 0) {
#pragma unroll 16
            for (int t = 0; t < 64; t++) { float v = ks[d][t]; acck += v*v; }
        }
    }
    g_Spart[(((long)sp*Bn + b)*HEADSn + h)*1024 + tid] = acc;
    if (d == 0) g_nqpart[((long)sp*Bn + b)*Cc + h*HDn + c] = accq;
    if (c == 0) g_nkpart[((long)sp*Bn + b)*Cc + h*HDn + d] = acck;
}

// ------------------------- mask generator + softmax --------------------------
__global__ void k_masksm(const float* __restrict__ fp_w,  const float* __restrict__ fp_b,
                         const float* __restrict__ mg1_w, const float* __restrict__ mg1_b,
                         const float* __restrict__ mg2_w, const float* __restrict__ mg2_b,
                         const float* __restrict__ temp)
{
    int h = blockIdx.x, b = blockIdx.y;
    int t = threadIdx.x;                          // 1024 threads
    __shared__ float comb[64], fin[256], h1[128];
    if (t < 32)           comb[t] = g_opm[b*Cc + h*HDn + t];
    else if (t < 64)      comb[t] = g_spm[b*Cc + h*HDn + (t-32)];
    if (t >= 128 && t < 256) fin[t] = g_pp[b*MHn + (t-128)];
    __syncthreads();
    if (t < 128) {
        float a = fp_b[t];
#pragma unroll 8
        for (int i = 0; i < 64; i++) a += comb[i]*fp_w[t*64 + i];
        fin[t] = a;
    }
    __syncthreads();
    if (t < 128) {
        float a = mg1_b[t];
        for (int i = 0; i < 256; i++) a += fin[i]*mg1_w[t*256 + i];
        h1[t] = fmaxf(a, 0.f);
    }
    __syncthreads();
    float a = mg2_b[t];
    for (int i = 0; i < 128; i++) a += h1[i]*mg2_w[t*128 + i];
    float mg = 1.f / (1.f + expf(-a));

    int c = t >> 5, d = t & 31;
    float s = 0.f, nq = 0.f, nk = 0.f;
#pragma unroll
    for (int sp = 0; sp < NSPLIT; sp++) {
        s  += g_Spart[(((long)sp*Bn + b)*HEADSn + h)*1024 + t];
        nq += g_nqpart[((long)sp*Bn + b)*Cc + h*HDn + c];
        nk += g_nkpart[((long)sp*Bn + b)*Cc + h*HDn + d];
    }
    float val = s / (fmaxf(sqrtf(nq), 1e-12f) * fmaxf(sqrtf(nk), 1e-12f));
    val = val * temp[h] * mg;
    float m = val;
    for (int o = 16; o > 0; o >>= 1) m = fmaxf(m, __shfl_xor_sync(0xffffffffu, m, o));
    float e = expf(val - m);
    float ssum = e;
    for (int o = 16; o > 0; o >>= 1) ssum += __shfl_xor_sync(0xffffffffu, ssum, o);
    g_probs[((long)b*HEADSn + h)*1024 + t] = e / ssum;
}

// ------------------------- M = o_w · blockdiag(probs) -----------------------
__global__ void k_M(const float* __restrict__ o_w)
{
    int b = blockIdx.x, o = blockIdx.y;
    int col = threadIdx.x;
    __shared__ float ow[256];
    __shared__ float pr[HEADSn*HDn*HDn];
    ow[col] = o_w[o*Cc + col];
    for (int i = col; i < HEADSn*HDn*HDn; i += 256) pr[i] = g_probs[(long)b*HEADSn*HDn*HDn + i];
    __syncthreads();
    int h = col >> 5, d = col & 31;
    float a = 0.f;
#pragma unroll 8
    for (int c = 0; c < 32; c++) a += ow[h*HDn + c] * pr[h*1024 + c*32 + d];
    g_M[((long)b*Cc + o)*Cc + col] = a;
}

// ------------------------- depthwise 3x3 + exact gelu gate (smem tiles) -----
__global__ __launch_bounds__(256)
void k_dwgelu(const float* __restrict__ tin, const float* __restrict__ dw)
{
    __shared__ float s1[10][36], s2[10][36];
    int zc = blockIdx.z;
    int b  = zc / HIDn;
    int c  = zc % HIDn;
    int x0 = blockIdx.x*32;
    int y0 = blockIdx.y*8;
    const float* p1 = tin + ((long)b*2*HIDn + c)*HWn;
    const float* p2 = p1 + (long)HIDn*HWn;

    for (int i = threadIdx.x; i < 340; i += 256) {
        int ry = i / 34, rx = i % 34;
        int yy = y0 + ry - 1, xx = x0 + rx - 1;
        bool ok = (yy >= 0) && (yy < Hh) && (xx >= 0) && (xx < Ww);
        long off = (long)yy*Ww + xx;
        s1[ry][rx] = ok ? p1[off] : 0.f;
        s2[ry][rx] = ok ? p2[off] : 0.f;
    }
    const float* w1 = dw + c*9;
    const float* w2 = dw + (c + HIDn)*9;
    float c1[9], c2[9];
#pragma unroll
    for (int i = 0; i < 9; i++) { c1[i] = w1[i]; c2[i] = w2[i]; }
    __syncthreads();

    int lx = threadIdx.x & 31, ly = threadIdx.x >> 5;
    float a1 = 0.f, a2 = 0.f;
#pragma unroll
    for (int ky = 0; ky < 3; ky++)
#pragma unroll
        for (int kx = 0; kx < 3; kx++) {
            a1 += s1[ly+ky][lx+kx]*c1[ky*3+kx];
            a2 += s2[ly+ky][lx+kx]*c2[ky*3+kx];
        }
    float g = 0.5f*a1*(1.f + erff(a1*0.70710678118654752f));
    float v = g * a2;
    long idx = ((long)b*HIDn + c)*HWn + (y0+ly)*Ww + (x0+lx);
    __nv_bfloat16 hh, ll;
    split1(v, hh, ll);
    g_g_h[idx] = hh;
    g_g_l[idx] = ll;
}

// ------------------------- vector copy (img2 passthrough) -------------------
__global__ void k_copy(const float* __restrict__ src, float* __restrict__ dst, long n4)
{
    long i = (long)blockIdx.x*blockDim.x + threadIdx.x;
    if (i < n4) ((float4*)dst)[i] = ((const float4*)src)[i];
}

// ----------------------------------------------------------------------------
extern "C" void kernel_launch(void* const* d_in, const int* in_sizes, int n_in,
                              void* d_out, int out_size)
{
    const float* img    = (const float*)d_in[0];
    const float* text   = (const float*)d_in[1];
    const float* lin1_w = (const float*)d_in[2];
    const float* lin1_b = (const float*)d_in[3];
    const float* lin3_w = (const float*)d_in[4];
    const float* lin3_b = (const float*)d_in[5];
    const float* c1w    = (const float*)d_in[6];
    const float* c1b    = (const float*)d_in[7];
    const float* cow    = (const float*)d_in[8];
    const float* cob    = (const float*)d_in[9];
    const float* n1w    = (const float*)d_in[10];
    const float* n1b    = (const float*)d_in[11];
    const float* n2w    = (const float*)d_in[12];
    const float* n2b    = (const float*)d_in[13];
    const float* n3w    = (const float*)d_in[14];
    const float* n3b    = (const float*)d_in[15];
    const float* q_w    = (const float*)d_in[16];
    const float* k_w    = (const float*)d_in[17];
    const float* v_w    = (const float*)d_in[18];
    const float* o_w    = (const float*)d_in[19];
    const float* temp   = (const float*)d_in[20];
    const float* fp_w   = (const float*)d_in[21];
    const float* fp_b   = (const float*)d_in[22];
    const float* pp_w   = (const float*)d_in[23];
    const float* pp_b   = (const float*)d_in[24];
    const float* mg1_w  = (const float*)d_in[25];
    const float* mg1_b  = (const float*)d_in[26];
    const float* mg2_w  = (const float*)d_in[27];
    const float* mg2_b  = (const float*)d_in[28];
    const float* pi_w   = (const float*)d_in[29];
    const float* dw_w   = (const float*)d_in[30];
    const float* po_w   = (const float*)d_in[31];
    float* out = (float*)d_out;

    cudaFuncSetAttribute(k_mma, cudaFuncAttributeMaxDynamicSharedMemorySize, MMA_SMEM);

    float *p_Weff, *p_beff, *p_qn, *p_q, *p_k, *p_att, *p_t, *p_opm, *p_spm, *p_M, *p_Watt;
    float *p_pp, *p_t1v, *p_t2v;
    cudaGetSymbolAddress((void**)&p_Weff, g_Weff);
    cudaGetSymbolAddress((void**)&p_beff, g_beff);
    cudaGetSymbolAddress((void**)&p_qn,   g_qn);
    cudaGetSymbolAddress((void**)&p_q,    g_q);
    cudaGetSymbolAddress((void**)&p_k,    g_k);
    cudaGetSymbolAddress((void**)&p_att,  g_att);
    cudaGetSymbolAddress((void**)&p_t,    g_t);
    cudaGetSymbolAddress((void**)&p_opm,  g_opm);
    cudaGetSymbolAddress((void**)&p_spm,  g_spm);
    cudaGetSymbolAddress((void**)&p_M,    g_M);
    cudaGetSymbolAddress((void**)&p_Watt, g_Watt);
    cudaGetSymbolAddress((void**)&p_pp,   g_pp);
    cudaGetSymbolAddress((void**)&p_t1v,  g_t1v);
    cudaGetSymbolAddress((void**)&p_t2v,  g_t2v);

    __nv_bfloat16 *imgh,*imgl,*qnh,*qnl,*knh,*knl,*xlh,*xll,*gh,*gl;
    __nv_bfloat16 *weh,*wel,*wah,*wal,*qwh,*qwl,*kwh,*kwl,*pih,*pil,*poh,*pol;
    cudaGetSymbolAddress((void**)&imgh, g_img_h); cudaGetSymbolAddress((void**)&imgl, g_img_l);
    cudaGetSymbolAddress((void**)&qnh,  g_qn_h);  cudaGetSymbolAddress((void**)&qnl,  g_qn_l);
    cudaGetSymbolAddress((void**)&knh,  g_kn_h);  cudaGetSymbolAddress((void**)&knl,  g_kn_l);
    cudaGetSymbolAddress((void**)&xlh,  g_xln_h); cudaGetSymbolAddress((void**)&xll,  g_xln_l);
    cudaGetSymbolAddress((void**)&gh,   g_g_h);   cudaGetSymbolAddress((void**)&gl,   g_g_l);
    cudaGetSymbolAddress((void**)&weh,  g_Weff_h);cudaGetSymbolAddress((void**)&wel,  g_Weff_l);
    cudaGetSymbolAddress((void**)&wah,  g_Watt_h);cudaGetSymbolAddress((void**)&wal,  g_Watt_l);
    cudaGetSymbolAddress((void**)&qwh,  g_qw_h);  cudaGetSymbolAddress((void**)&qwl,  g_qw_l);
    cudaGetSymbolAddress((void**)&kwh,  g_kw_h);  cudaGetSymbolAddress((void**)&kwl,  g_kw_l);
    cudaGetSymbolAddress((void**)&pih,  g_piw_h); cudaGetSymbolAddress((void**)&pil,  g_piw_l);
    cudaGetSymbolAddress((void**)&poh,  g_pow_h); cudaGetSymbolAddress((void**)&pol,  g_pow_l);

    // 0. input / static weight splits
    k_split<<<16384, 256>>>(img,  imgh, imgl, NIMG/4);
    k_split<<<64,    256>>>(q_w,  qwh,  qwl,  (long)Cc*Cc/4);
    k_split<<<64,    256>>>(k_w,  kwh,  kwl,  (long)Cc*Cc/4);
    k_split<<<340,   256>>>(pi_w, pih,  pil,  (long)2*HIDn*Cc/4);
    k_split<<<170,   256>>>(po_w, poh,  pol,  (long)Cc*HIDn/4);

    // 1. text MLP in exact serial order (rank-safe), spread across SMs
    k_lin<<<dim3(LINn/32, Bn), 32>>>(lin1_w, text,  lin1_b, p_t1v, LINn, LINn);
    k_lin<<<dim3(MHn/32,  Bn), 32>>>(pp_w,   text,  pp_b,   p_pp,  MHn,  LINn);
    k_lin<<<dim3(LINn/32, Bn), 32>>>(lin3_w, p_t1v, lin3_b, p_t2v, LINn, LINn);
    k_rank<<<Bn, LINn>>>(p_t2v);
    // 2. effective shuffle weight/bias
    k_beff<<<Bn, Cc>>>(cow, cob, c1b);
    k_weff<<<dim3(16,16,Bn), dim3(16,16)>>>(cow, c1w);
    k_split<<<256, 256>>>(p_Weff, weh, wel, (long)Bn*Cc*Cc/4);
    // 3. qn_raw = W_eff @ img + b_eff ; LN -> hi/lo splits
    k_mma<<<dim3(128,2,Bn), 256, MMA_SMEM>>>(weh, wel, imgh, imgl, p_qn, p_beff, nullptr,
                                             Cc, Cc, HWn, (long)Cc*Cc, CHW, CHW, Cc, 0);
    k_ln<<<dim3(16,Bn), 256>>>(p_qn, qnh, qnl, n1w, n1b);
    k_ln<<<dim3(16,Bn), 256>>>(img,  knh, knl, n2w, n2b);
    // 4. q = q_w@qn, k = k_w@kn (fp32 out for scores)
    k_mma<<<dim3(128,2,Bn), 256, MMA_SMEM>>>(qwh, qwl, qnh, qnl, p_q, nullptr, nullptr,
                                             Cc, Cc, HWn, 0, CHW, CHW, 0, 0);
    k_mma<<<dim3(128,2,Bn), 256, MMA_SMEM>>>(kwh, kwl, knh, knl, p_k, nullptr, nullptr,
                                             Cc, Cc, HWn, 0, CHW, CHW, 0, 0);
    // 5. channel means
    k_chmean<<<dim3(Cc,Bn), 256>>>(knh, knl, p_opm);
    k_chmean<<<dim3(Cc,Bn), 256>>>(qnh, qnl, p_spm);
    // 6. per-head scores partials + norms
    k_scores<<<dim3(NSPLIT, HEADSn, Bn), dim3(32,32)>>>(p_q, p_k);
    // 7. mask generator + softmax -> probs
    k_masksm<<<dim3(HEADSn, Bn), 1024>>>(fp_w, fp_b, mg1_w, mg1_b, mg2_w, mg2_b, temp);
    // 8. M = o_w · blockdiag(probs);  W_att = M @ v_w (small, scalar GEMM)
    k_M<<<dim3(Bn, Cc), 256>>>(o_w);
    k_gemm<<<dim3(2,2,Bn), 256>>>(p_M, v_w, p_Watt, Cc, Cc, Cc,
                                  (long)Cc*Cc, 0, (long)Cc*Cc);
    k_split<<<256, 256>>>(p_Watt, wah, wal, (long)Bn*Cc*Cc/4);
    // 9. att = W_att @ kn
    k_mma<<<dim3(128,2,Bn), 256, MMA_SMEM>>>(wah, wal, knh, knl, p_att, nullptr, nullptr,
                                             Cc, Cc, HWn, (long)Cc*Cc, CHW, CHW, 0, 0);
    // 10. FFN
    k_ln<<<dim3(16,Bn), 256>>>(p_att, xlh, xll, n3w, n3b);
    k_mma<<<dim3(128,11,Bn), 256, MMA_SMEM>>>(pih, pil, xlh, xll, p_t, nullptr, nullptr,
                                              2*HIDn, Cc, HWn, 0, CHW, (long)2*HIDn*HWn, 0, 0);
    k_dwgelu<<<dim3(4,16,Bn*HIDn), 256>>>(p_t, dw_w);
    k_mma<<<dim3(128,2,Bn), 256, MMA_SMEM>>>(poh, pol, gh, gl, out, nullptr, p_att,
                                             Cc, HIDn, HWn, 0, (long)HIDn*HWn, CHW, 0, CHW);
    // 11. second tuple output: img2 passthrough
    if ((long)out_size >= 2*NIMG)
        k_copy<<<16384, 256>>>(img, out + NIMG, NIMG/4);
}

// round 16
// speedup vs baseline: 1.1436x; 1.0694x over previous
#include <cuda_runtime.h>
#include <cuda_bf16.h>
#include <cuda_fp16.h>
#include <math.h>
#include <stdint.h>

#define Bn     4
#define Cc     256
#define Hh     128
#define Ww     128
#define HWn    16384
#define HEADSn 8
#define HDn    32
#define LINn   512
#define HIDn   680
#define MHn    128
#define NSPLIT 8

#define CHW    ((long)Cc*HWn)          // 4194304
#define NIMG   ((long)Bn*Cc*HWn)       // 16777216

// ------------------------- scratch (static device memory) -------------------
__device__ int   g_idx [Bn*LINn];
__device__ float g_pp  [Bn*MHn];
__device__ float g_t1v [Bn*LINn];
__device__ float g_t2v [Bn*LINn];
__device__ float g_Weff[Bn*Cc*Cc];
__device__ float g_beff[Bn*Cc];
__device__ float g_qn  [Bn*Cc*HWn];
__device__ float g_q   [Bn*Cc*HWn];
__device__ float g_k   [Bn*Cc*HWn];
__device__ float g_att [Bn*Cc*HWn];
__device__ float g_t   [Bn*2*HIDn*HWn];
__device__ float g_Spart [NSPLIT*Bn*HEADSn*HDn*HDn];
__device__ float g_nqpart[NSPLIT*Bn*Cc];
__device__ float g_nkpart[NSPLIT*Bn*Cc];
__device__ float g_opm [Bn*Cc];
__device__ float g_spm [Bn*Cc];
__device__ float g_probs[Bn*HEADSn*HDn*HDn];
__device__ float g_M   [Bn*Cc*Cc];
__device__ float g_Watt[Bn*Cc*Cc];

// bf16 hi/lo split buffers (3-term path: Weff/q/k/att)
__device__ __nv_bfloat16 g_img_h[NIMG],  g_img_l[NIMG];
__device__ __nv_bfloat16 g_qn_h [NIMG],  g_qn_l [NIMG];
__device__ __nv_bfloat16 g_kn_h [NIMG],  g_kn_l [NIMG];
__device__ __nv_bfloat16 g_Weff_h[Bn*Cc*Cc], g_Weff_l[Bn*Cc*Cc];
__device__ __nv_bfloat16 g_Watt_h[Bn*Cc*Cc], g_Watt_l[Bn*Cc*Cc];
__device__ __nv_bfloat16 g_qw_h[Cc*Cc],  g_qw_l[Cc*Cc];
__device__ __nv_bfloat16 g_kw_h[Cc*Cc],  g_kw_l[Cc*Cc];

// fp16 buffers (2-term FFN path: pi/po)
__device__ __half g_xln16h[NIMG], g_xln16l[NIMG];
__device__ __half g_g16h[(long)Bn*HIDn*HWn], g_g16l[(long)Bn*HIDn*HWn];
__device__ __half g_piw16[2*HIDn*Cc];
__device__ __half g_pow16[Cc*HIDn];

// ------------------------- PTX helpers --------------------------------------
__device__ __forceinline__ uint32_t s2u32(const void* p){
    uint32_t r;
    asm("{.reg .u64 t; cvta.to.shared.u64 t, %1; cvt.u32.u64 %0, t;}"
        : "=r"(r) : "l"(p));
    return r;
}
__device__ __forceinline__ void ldsm_x4(uint32_t* r, uint32_t a){
    asm volatile("ldmatrix.sync.aligned.m8n8.x4.shared.b16 {%0,%1,%2,%3},[%4];"
        : "=r"(r[0]),"=r"(r[1]),"=r"(r[2]),"=r"(r[3]) : "r"(a));
}
__device__ __forceinline__ void ldsm_x4t(uint32_t* r, uint32_t a){
    asm volatile("ldmatrix.sync.aligned.m8n8.x4.trans.shared.b16 {%0,%1,%2,%3},[%4];"
        : "=r"(r[0]),"=r"(r[1]),"=r"(r[2]),"=r"(r[3]) : "r"(a));
}
__device__ __forceinline__ void mma16816(float* c, const uint32_t* a, const uint32_t* b){
    asm volatile("mma.sync.aligned.m16n8k16.row.col.f32.bf16.bf16.f32 "
        "{%0,%1,%2,%3},{%4,%5,%6,%7},{%8,%9},{%0,%1,%2,%3};"
        : "+f"(c[0]),"+f"(c[1]),"+f"(c[2]),"+f"(c[3])
        : "r"(a[0]),"r"(a[1]),"r"(a[2]),"r"(a[3]),"r"(b[0]),"r"(b[1]));
}
__device__ __forceinline__ void mma16816h(float* c, const uint32_t* a, const uint32_t* b){
    asm volatile("mma.sync.aligned.m16n8k16.row.col.f32.f16.f16.f32 "
        "{%0,%1,%2,%3},{%4,%5,%6,%7},{%8,%9},{%0,%1,%2,%3};"
        : "+f"(c[0]),"+f"(c[1]),"+f"(c[2]),"+f"(c[3])
        : "r"(a[0]),"r"(a[1]),"r"(a[2]),"r"(a[3]),"r"(b[0]),"r"(b[1]));
}
__device__ __forceinline__ void split1(float v, __nv_bfloat16& h, __nv_bfloat16& l){
    h = __float2bfloat16(v);
    l = __float2bfloat16(v - __bfloat162float(h));
}
__device__ __forceinline__ void split1h(float v, __half& h, __half& l){
    h = __float2half_rn(v);
    l = __float2half_rn(v - __half2float(h));
}
__device__ __forceinline__ void cpa16(uint32_t s, const void* g, bool v){
    int sz = v ? 16 : 0;
    asm volatile("cp.async.cg.shared.global [%0], [%1], 16, %2;"
                 :: "r"(s), "l"(g), "r"(sz));
}
#define CP_COMMIT() asm volatile("cp.async.commit_group;")
#define CP_WAIT(n)  asm volatile("cp.async.wait_group %0;" :: "n"(n))

// ------------------------- serial-order linear layers ------------------------
__global__ void k_lin(const float* __restrict__ W, const float* __restrict__ x,
                      const float* __restrict__ bias, float* __restrict__ y,
                      int Odim, int In)
{
    int b = blockIdx.y;
    int o = blockIdx.x*32 + threadIdx.x;
    if (o >= Odim) return;
    const float* xr = x + (long)b*In;
    const float* wr = W + (long)o*In;
    float a = bias[o];
#pragma unroll 8
    for (int i = 0; i < In; i++) a += xr[i]*wr[i];
    y[(long)b*Odim + o] = a;
}

// ------------------------- stable descending rank (== top_k indices) --------
__global__ void k_rank(const float* __restrict__ t2)
{
    int b = blockIdx.x, t = threadIdx.x;
    __shared__ float s[LINn];
    s[t] = t2[b*LINn + t];
    __syncthreads();
    float v = s[t];
    int rank = 0;
    for (int i = 0; i < LINn; i++) {
        float u = s[i];
        rank += (u > v) || (u == v && i < t);
    }
    g_idx[b*LINn + rank] = t;
}

// ------------------------- effective shuffle weight -------------------------
__global__ void k_beff(const float* __restrict__ cow, const float* __restrict__ cob,
                       const float* __restrict__ c1b)
{
    int b = blockIdx.x, o = threadIdx.x;
    float a = cob[o];
    for (int j = 0; j < 2*Cc; j++) a += cow[o*2*Cc + j] * c1b[g_idx[b*LINn + j]];
    g_beff[b*Cc + o] = a;
}

__global__ void k_weff(const float* __restrict__ cow, const float* __restrict__ c1w)
{
    int b = blockIdx.z;
    int o = blockIdx.y*16 + threadIdx.y;
    int i = blockIdx.x*16 + threadIdx.x;
    __shared__ int sidx[2*Cc];
    int t = threadIdx.y*16 + threadIdx.x;
    sidx[t]       = g_idx[b*LINn + t];
    sidx[t + 256] = g_idx[b*LINn + t + 256];
    __syncthreads();
    float a = 0.f;
    for (int j = 0; j < 2*Cc; j++) a += cow[o*2*Cc + j] * c1w[sidx[j]*Cc + i];
    g_Weff[((long)b*Cc + o)*Cc + i] = a;
}

// ------------------------- elementwise fp32 -> (hi,lo) bf16 -----------------
__global__ void k_split(const float* __restrict__ s, __nv_bfloat16* __restrict__ h,
                        __nv_bfloat16* __restrict__ l, long n4)
{
    long i = (long)blockIdx.x*blockDim.x + threadIdx.x;
    if (i >= n4) return;
    float4 v = ((const float4*)s)[i];
    __nv_bfloat16 h0,h1,h2,h3,l0,l1,l2,l3;
    split1(v.x,h0,l0); split1(v.y,h1,l1); split1(v.z,h2,l2); split1(v.w,h3,l3);
    ((__nv_bfloat162*)h)[i*2]   = __nv_bfloat162(h0,h1);
    ((__nv_bfloat162*)h)[i*2+1] = __nv_bfloat162(h2,h3);
    ((__nv_bfloat162*)l)[i*2]   = __nv_bfloat162(l0,l1);
    ((__nv_bfloat162*)l)[i*2+1] = __nv_bfloat162(l2,l3);
}

// ------------------------- elementwise fp32 -> single fp16 ------------------
__global__ void k_splith(const float* __restrict__ s, __half* __restrict__ h, long n4)
{
    long i = (long)blockIdx.x*blockDim.x + threadIdx.x;
    if (i >= n4) return;
    float4 v = ((const float4*)s)[i];
    ((__half2*)h)[i*2]   = __floats2half2_rn(v.x, v.y);
    ((__half2*)h)[i*2+1] = __floats2half2_rn(v.z, v.w);
}

// ------------------------- split-bf16 tensor-core GEMM (cp.async DB, 3-term) -
#define WP 40
#define XP 136
#define MMA_SMEM (2*2*128*WP*2 + 2*2*32*XP*2)   // 75776
__global__ __launch_bounds__(256, 2)
void k_mma(const __nv_bfloat16* __restrict__ WhiG, const __nv_bfloat16* __restrict__ WloG,
           const __nv_bfloat16* __restrict__ XhiG, const __nv_bfloat16* __restrict__ XloG,
           float* __restrict__ Cg, const float* __restrict__ biasg,
           const float* __restrict__ resg,
           int M, int K, int N, long sW, long sX, long sC, long sB, long sR)
{
    extern __shared__ __align__(16) unsigned char dyn[];
    uint32_t aW = s2u32(dyn);
    uint32_t aX = aW + 40960;

    int bz = blockIdx.z;
    const __nv_bfloat16* Wh = WhiG + (long)bz*sW;
    const __nv_bfloat16* Wl = WloG + (long)bz*sW;
    const __nv_bfloat16* Xh = XhiG + (long)bz*sX;
    const __nv_bfloat16* Xl = XloG + (long)bz*sX;
    float* C = Cg + (long)bz*sC;
    const float* bias = biasg ? biasg + (long)bz*sB : nullptr;
    const float* res  = resg  ? resg  + (long)bz*sR : nullptr;

    int m0 = blockIdx.y*128, n0 = blockIdx.x*128;
    int tid = threadIdx.x, lane = tid & 31, w = tid >> 5;
    int wr = w >> 2, wc = w & 3;

    int wrow = tid >> 2;
    int wcol = (tid & 3) * 8;
    int xrow = tid >> 4;
    int xcol = (tid & 15) * 8;

    auto issue = [&](int kt, int buf){
        long k0 = (long)kt*32;
#pragma unroll
        for (int p = 0; p < 2; p++) {
            int gm = m0 + wrow + p*64; if (gm >= M) gm = M - 1;
            long kk = k0 + wcol;
            bool vw = (kk + 8 <= (long)K);
            long kwc = vw ? kk : 0;
            uint32_t dW = aW + buf*20480 + (wrow + p*64)*80 + wcol*2;
            cpa16(dW,          Wh + (long)gm*K + kwc, vw);
            cpa16(dW + 10240,  Wl + (long)gm*K + kwc, vw);
            long gk = k0 + xrow + p*16;
            bool vx = (gk < (long)K);
            long gkc = vx ? gk : 0;
            uint32_t dX = aX + buf*17408 + (xrow + p*16)*272 + xcol*2;
            cpa16(dX,         Xh + gkc*N + n0 + xcol, vx);
            cpa16(dX + 8704,  Xl + gkc*N + n0 + xcol, vx);
        }
        CP_COMMIT();
    };

    int arow = wr*64 + (lane & 15);
    int acol = (lane >> 4) * 8;
    int brow = ((lane >> 3) & 1)*8 + (lane & 7);
    int bcol = wc*32 + (lane >> 4)*8;

    float acc[4][4][4];
#pragma unroll
    for (int i = 0; i < 4; i++)
#pragma unroll
        for (int j = 0; j < 4; j++)
#pragma unroll
            for (int q = 0; q < 4; q++) acc[i][j][q] = 0.f;

    int nt = (K + 31) >> 5;
    issue(0, 0);
    for (int kt = 0; kt < nt; kt++) {
        int buf = kt & 1;
        if (kt + 1 < nt) { issue(kt + 1, buf ^ 1); CP_WAIT(1); }
        else             { CP_WAIT(0); }
        __syncthreads();
        uint32_t bWh = aW + buf*20480, bWl = bWh + 10240;
        uint32_t bXh = aX + buf*17408, bXl = bXh + 8704;
#pragma unroll
        for (int ks = 0; ks < 32; ks += 16) {
            uint32_t bh[4][2], bl[4][2], tmp[4];
#pragma unroll
            for (int np = 0; np < 2; np++) {
                uint32_t off = (uint32_t)((ks + brow)*272 + (bcol + np*16)*2);
                ldsm_x4t(tmp, bXh + off);
                bh[np*2][0]=tmp[0]; bh[np*2][1]=tmp[1];
                bh[np*2+1][0]=tmp[2]; bh[np*2+1][1]=tmp[3];
                ldsm_x4t(tmp, bXl + off);
                bl[np*2][0]=tmp[0]; bl[np*2][1]=tmp[1];
                bl[np*2+1][0]=tmp[2]; bl[np*2+1][1]=tmp[3];
            }
#pragma unroll
            for (int mt = 0; mt < 4; mt++) {
                uint32_t ah[4], al[4];
                uint32_t off = (uint32_t)((arow + mt*16)*80 + (ks + acol)*2);
                ldsm_x4(ah, bWh + off);
                ldsm_x4(al, bWl + off);
#pragma unroll
                for (int ntl = 0; ntl < 4; ntl++) {
                    mma16816(acc[mt][ntl], ah, bh[ntl]);
                    mma16816(acc[mt][ntl], ah, bl[ntl]);
                    mma16816(acc[mt][ntl], al, bh[ntl]);
                }
            }
        }
        __syncthreads();
    }

    int r = lane >> 2, cp = (lane & 3)*2;
#pragma unroll
    for (int mt = 0; mt < 4; mt++) {
        int mA = m0 + wr*64 + mt*16 + r;
        int mB = mA + 8;
#pragma unroll
        for (int ntl = 0; ntl < 4; ntl++) {
            int nn = n0 + wc*32 + ntl*8 + cp;
            if (mA < M) {
                float bv = bias ? bias[mA] : 0.f;
                float2 v = make_float2(acc[mt][ntl][0] + bv, acc[mt][ntl][1] + bv);
                if (res) { v.x += res[(long)mA*N + nn]; v.y += res[(long)mA*N + nn + 1]; }
                *(float2*)(C + (long)mA*N + nn) = v;
            }
            if (mB < M) {
                float bv = bias ? bias[mB] : 0.f;
                float2 v = make_float2(acc[mt][ntl][2] + bv, acc[mt][ntl][3] + bv);
                if (res) { v.x += res[(long)mB*N + nn]; v.y += res[(long)mB*N + nn + 1]; }
                *(float2*)(C + (long)mB*N + nn) = v;
            }
        }
    }
}

// ------------------------- fp16 2-term tensor-core GEMM (FFN path) ----------
// C = Wh @ (Xh + Xl), fp32 accum. W:[M,K] fp16 rm, X hi/lo:[K,N] fp16 rm.
#define MMAH_SMEM (2*128*WP*2 + 2*2*32*XP*2)   // 20480 + 34816 = 55296
__global__ __launch_bounds__(256, 2)
void k_mmah(const __half* __restrict__ WG,
            const __half* __restrict__ XhiG, const __half* __restrict__ XloG,
            float* __restrict__ Cg, const float* __restrict__ resg,
            int M, int K, int N, long sW, long sX, long sC, long sR)
{
    extern __shared__ __align__(16) unsigned char dyn[];
    uint32_t aW = s2u32(dyn);
    uint32_t aX = aW + 20480;

    int bz = blockIdx.z;
    const __half* W  = WG   + (long)bz*sW;
    const __half* Xh = XhiG + (long)bz*sX;
    const __half* Xl = XloG + (long)bz*sX;
    float* C = Cg + (long)bz*sC;
    const float* res = resg ? resg + (long)bz*sR : nullptr;

    int m0 = blockIdx.y*128, n0 = blockIdx.x*128;
    int tid = threadIdx.x, lane = tid & 31, w = tid >> 5;
    int wr = w >> 2, wc = w & 3;

    int wrow = tid >> 2;
    int wcol = (tid & 3) * 8;
    int xrow = tid >> 4;
    int xcol = (tid & 15) * 8;

    auto issue = [&](int kt, int buf){
        long k0 = (long)kt*32;
#pragma unroll
        for (int p = 0; p < 2; p++) {
            int gm = m0 + wrow + p*64; if (gm >= M) gm = M - 1;
            long kk = k0 + wcol;
            bool vw = (kk + 8 <= (long)K);
            long kwc = vw ? kk : 0;
            uint32_t dW = aW + buf*10240 + (wrow + p*64)*80 + wcol*2;
            cpa16(dW, W + (long)gm*K + kwc, vw);
            long gk = k0 + xrow + p*16;
            bool vx = (gk < (long)K);
            long gkc = vx ? gk : 0;
            uint32_t dX = aX + buf*17408 + (xrow + p*16)*272 + xcol*2;
            cpa16(dX,         Xh + gkc*N + n0 + xcol, vx);
            cpa16(dX + 8704,  Xl + gkc*N + n0 + xcol, vx);
        }
        CP_COMMIT();
    };

    int arow = wr*64 + (lane & 15);
    int acol = (lane >> 4) * 8;
    int brow = ((lane >> 3) & 1)*8 + (lane & 7);
    int bcol = wc*32 + (lane >> 4)*8;

    float acc[4][4][4];
#pragma unroll
    for (int i = 0; i < 4; i++)
#pragma unroll
        for (int j = 0; j < 4; j++)
#pragma unroll
            for (int q = 0; q < 4; q++) acc[i][j][q] = 0.f;

    int nt = (K + 31) >> 5;
    issue(0, 0);
    for (int kt = 0; kt < nt; kt++) {
        int buf = kt & 1;
        if (kt + 1 < nt) { issue(kt + 1, buf ^ 1); CP_WAIT(1); }
        else             { CP_WAIT(0); }
        __syncthreads();
        uint32_t bW  = aW + buf*10240;
        uint32_t bXh = aX + buf*17408, bXl = bXh + 8704;
#pragma unroll
        for (int ks = 0; ks < 32; ks += 16) {
            uint32_t bh[4][2], bl[4][2], tmp[4];
#pragma unroll
            for (int np = 0; np < 2; np++) {
                uint32_t off = (uint32_t)((ks + brow)*272 + (bcol + np*16)*2);
                ldsm_x4t(tmp, bXh + off);
                bh[np*2][0]=tmp[0]; bh[np*2][1]=tmp[1];
                bh[np*2+1][0]=tmp[2]; bh[np*2+1][1]=tmp[3];
                ldsm_x4t(tmp, bXl + off);
                bl[np*2][0]=tmp[0]; bl[np*2][1]=tmp[1];
                bl[np*2+1][0]=tmp[2]; bl[np*2+1][1]=tmp[3];
            }
#pragma unroll
            for (int mt = 0; mt < 4; mt++) {
                uint32_t ah[4];
                uint32_t off = (uint32_t)((arow + mt*16)*80 + (ks + acol)*2);
                ldsm_x4(ah, bW + off);
#pragma unroll
                for (int ntl = 0; ntl < 4; ntl++) {
                    mma16816h(acc[mt][ntl], ah, bh[ntl]);
                    mma16816h(acc[mt][ntl], ah, bl[ntl]);
                }
            }
        }
        __syncthreads();
    }

    int r = lane >> 2, cp = (lane & 3)*2;
#pragma unroll
    for (int mt = 0; mt < 4; mt++) {
        int mA = m0 + wr*64 + mt*16 + r;
        int mB = mA + 8;
#pragma unroll
        for (int ntl = 0; ntl < 4; ntl++) {
            int nn = n0 + wc*32 + ntl*8 + cp;
            if (mA < M) {
                float2 v = make_float2(acc[mt][ntl][0], acc[mt][ntl][1]);
                if (res) { v.x += res[(long)mA*N + nn]; v.y += res[(long)mA*N + nn + 1]; }
                *(float2*)(C + (long)mA*N + nn) = v;
            }
            if (mB < M) {
                float2 v = make_float2(acc[mt][ntl][2], acc[mt][ntl][3]);
                if (res) { v.x += res[(long)mB*N + nn]; v.y += res[(long)mB*N + nn + 1]; }
                *(float2*)(C + (long)mB*N + nn) = v;
            }
        }
    }
}

// ------------------------- scalar SGEMM (small Watt GEMM only) --------------
__global__ __launch_bounds__(256)
void k_gemm(const float* __restrict__ Wg, const float* __restrict__ Xg,
            float* __restrict__ Cg, int M, int K, int N, long sW, long sX, long sC)
{
    int bz = blockIdx.z;
    const float* W = Wg + (long)bz*sW;
    const float* X = Xg + (long)bz*sX;
    float*       C = Cg + (long)bz*sC;
    int m0 = blockIdx.y*128, n0 = blockIdx.x*128;
    __shared__ float Ws[8][128];
    __shared__ float Xs[8][128];
    int tid = threadIdx.x;
    int tx = tid & 15, ty = tid >> 4;
    float acc[8][8];
#pragma unroll
    for (int i = 0; i < 8; i++)
#pragma unroll
        for (int j = 0; j < 8; j++) acc[i][j] = 0.f;
    int wm = tid >> 1, wk = (tid & 1)*4;
    int xk = tid >> 5, xn = (tid & 31)*4;
    for (int k0 = 0; k0 < K; k0 += 8) {
        float4 wv = *(const float4*)(W + (long)(m0 + wm)*K + k0 + wk);
        Ws[wk+0][wm] = wv.x; Ws[wk+1][wm] = wv.y;
        Ws[wk+2][wm] = wv.z; Ws[wk+3][wm] = wv.w;
        *(float4*)&Xs[xk][xn] = *(const float4*)(X + (long)(k0 + xk)*N + n0 + xn);
        __syncthreads();
#pragma unroll
        for (int k = 0; k < 8; k++) {
            float a[8], bb[8];
#pragma unroll
            for (int i = 0; i < 4; i++) { a[i] = Ws[k][ty*4+i]; a[i+4] = Ws[k][64+ty*4+i]; }
#pragma unroll
            for (int j = 0; j < 4; j++) { bb[j] = Xs[k][tx*4+j]; bb[j+4] = Xs[k][64+tx*4+j]; }
#pragma unroll
            for (int i = 0; i < 8; i++)
#pragma unroll
                for (int j = 0; j < 8; j++) acc[i][j] += a[i]*bb[j];
        }
        __syncthreads();
    }
#pragma unroll
    for (int i = 0; i < 8; i++) {
        int m = m0 + ((i < 4) ? ty*4 + i : 64 + ty*4 + (i-4));
        float* crow = C + (long)m*N + n0;
        *(float4*)(crow + tx*4)      = make_float4(acc[i][0],acc[i][1],acc[i][2],acc[i][3]);
        *(float4*)(crow + 64 + tx*4) = make_float4(acc[i][4],acc[i][5],acc[i][6],acc[i][7]);
    }
}

// ------------------------- channel LayerNorm -> hi/lo bf16 ------------------
__global__ void k_ln(const float* __restrict__ src,
                     __nv_bfloat16* __restrict__ dh, __nv_bfloat16* __restrict__ dl,
                     const float* __restrict__ w, const float* __restrict__ bias)
{
    int b = blockIdx.y;
    int p4 = blockIdx.x*blockDim.x + threadIdx.x;
    const float4* s = (const float4*)(src + (long)b*CHW) + p4;
    float4 sum = make_float4(0.f,0.f,0.f,0.f);
    float4 sq  = make_float4(0.f,0.f,0.f,0.f);
    for (int c = 0; c < Cc; c++) {
        float4 x = s[(long)c*(HWn/4)];
        sum.x += x.x; sum.y += x.y; sum.z += x.z; sum.w += x.w;
        sq.x += x.x*x.x; sq.y += x.y*x.y; sq.z += x.z*x.z; sq.w += x.w*x.w;
    }
    const float inv = 1.f/Cc;
    float4 mu = make_float4(sum.x*inv, sum.y*inv, sum.z*inv, sum.w*inv);
    float4 rs;
    rs.x = rsqrtf(sq.x*inv - mu.x*mu.x + 1e-5f);
    rs.y = rsqrtf(sq.y*inv - mu.y*mu.y + 1e-5f);
    rs.z = rsqrtf(sq.z*inv - mu.z*mu.z + 1e-5f);
    rs.w = rsqrtf(sq.w*inv - mu.w*mu.w + 1e-5f);
    long base = (long)b*CHW + (long)p4*4;
    for (int c = 0; c < Cc; c++) {
        float4 x = s[(long)c*(HWn/4)];
        float wc = w[c], bc = bias[c];
        float4 o;
        o.x = (x.x - mu.x)*rs.x*wc + bc;
        o.y = (x.y - mu.y)*rs.y*wc + bc;
        o.z = (x.z - mu.z)*rs.z*wc + bc;
        o.w = (x.w - mu.w)*rs.w*wc + bc;
        __nv_bfloat16 h0,h1,h2,h3,l0,l1,l2,l3;
        split1(o.x,h0,l0); split1(o.y,h1,l1); split1(o.z,h2,l2); split1(o.w,h3,l3);
        long idx2 = (base + (long)c*HWn) >> 1;
        ((__nv_bfloat162*)dh)[idx2]   = __nv_bfloat162(h0,h1);
        ((__nv_bfloat162*)dh)[idx2+1] = __nv_bfloat162(h2,h3);
        ((__nv_bfloat162*)dl)[idx2]   = __nv_bfloat162(l0,l1);
        ((__nv_bfloat162*)dl)[idx2+1] = __nv_bfloat162(l2,l3);
    }
}

// ------------------------- channel LayerNorm -> hi/lo fp16 ------------------
__global__ void k_lnh(const float* __restrict__ src,
                      __half* __restrict__ dh, __half* __restrict__ dl,
                      const float* __restrict__ w, const float* __restrict__ bias)
{
    int b = blockIdx.y;
    int p4 = blockIdx.x*blockDim.x + threadIdx.x;
    const float4* s = (const float4*)(src + (long)b*CHW) + p4;
    float4 sum = make_float4(0.f,0.f,0.f,0.f);
    float4 sq  = make_float4(0.f,0.f,0.f,0.f);
    for (int c = 0; c < Cc; c++) {
        float4 x = s[(long)c*(HWn/4)];
        sum.x += x.x; sum.y += x.y; sum.z += x.z; sum.w += x.w;
        sq.x += x.x*x.x; sq.y += x.y*x.y; sq.z += x.z*x.z; sq.w += x.w*x.w;
    }
    const float inv = 1.f/Cc;
    float4 mu = make_float4(sum.x*inv, sum.y*inv, sum.z*inv, sum.w*inv);
    float4 rs;
    rs.x = rsqrtf(sq.x*inv - mu.x*mu.x + 1e-5f);
    rs.y = rsqrtf(sq.y*inv - mu.y*mu.y + 1e-5f);
    rs.z = rsqrtf(sq.z*inv - mu.z*mu.z + 1e-5f);
    rs.w = rsqrtf(sq.w*inv - mu.w*mu.w + 1e-5f);
    long base = (long)b*CHW + (long)p4*4;
    for (int c = 0; c < Cc; c++) {
        float4 x = s[(long)c*(HWn/4)];
        float wc = w[c], bc = bias[c];
        float4 o;
        o.x = (x.x - mu.x)*rs.x*wc + bc;
        o.y = (x.y - mu.y)*rs.y*wc + bc;
        o.z = (x.z - mu.z)*rs.z*wc + bc;
        o.w = (x.w - mu.w)*rs.w*wc + bc;
        __half h0,h1,h2,h3,l0,l1,l2,l3;
        split1h(o.x,h0,l0); split1h(o.y,h1,l1); split1h(o.z,h2,l2); split1h(o.w,h3,l3);
        long idx2 = (base + (long)c*HWn) >> 1;
        ((__half2*)dh)[idx2]   = __halves2half2(h0,h1);
        ((__half2*)dh)[idx2+1] = __halves2half2(h2,h3);
        ((__half2*)dl)[idx2]   = __halves2half2(l0,l1);
        ((__half2*)dl)[idx2+1] = __halves2half2(l2,l3);
    }
}

// ------------------------- per-channel mean over HW (hi/lo bf16 input) ------
__global__ void k_chmean(const __nv_bfloat16* __restrict__ hi,
                         const __nv_bfloat16* __restrict__ lo, float* __restrict__ dst)
{
    int b = blockIdx.y, c = blockIdx.x, t = threadIdx.x;
    const __nv_bfloat162* h2 = (const __nv_bfloat162*)(hi + ((long)b*Cc + c)*HWn);
    const __nv_bfloat162* l2 = (const __nv_bfloat162*)(lo + ((long)b*Cc + c)*HWn);
    float a = 0.f;
    for (int i = t; i < HWn/2; i += 256) {
        __nv_bfloat162 hv = h2[i], lv = l2[i];
        a += __bfloat162float(hv.x) + __bfloat162float(hv.y)
           + __bfloat162float(lv.x) + __bfloat162float(lv.y);
    }
    __shared__ float r[256];
    r[t] = a; __syncthreads();
    for (int o = 128; o > 0; o >>= 1) { if (t < o) r[t] += r[t+o]; __syncthreads(); }
    if (t == 0) dst[b*Cc + c] = r[0] * (1.f/HWn);
}

// ------------------------- per-head QK^T partial + row norms ----------------
__global__ void k_scores(const float* __restrict__ q, const float* __restrict__ k)
{
    int sp = blockIdx.x, h = blockIdx.y, b = blockIdx.z;
    int d = threadIdx.x, c = threadIdx.y;
    int tid = c*32 + d;
    const float* Q  = q + ((long)(b*Cc + h*HDn))*HWn;
    const float* Kp = k + ((long)(b*Cc + h*HDn))*HWn;
    __shared__ float qs[32][65], ks[32][65];
    const int chunk = HWn / NSPLIT;
    int n0 = sp*chunk;
    float acc = 0.f, accq = 0.f, acck = 0.f;
    int lr = tid >> 5;
    int lc = (tid & 31) * 2;
    for (int n = n0; n < n0 + chunk; n += 64) {
        float2 qv = *(const float2*)(Q  + (long)lr*HWn + n + lc);
        float2 kv = *(const float2*)(Kp + (long)lr*HWn + n + lc);
        __syncthreads();
        qs[lr][lc] = qv.x; qs[lr][lc+1] = qv.y;
        ks[lr][lc] = kv.x; ks[lr][lc+1] = kv.y;
        __syncthreads();
#pragma unroll 16
        for (int t = 0; t < 64; t++) acc += qs[c][t]*ks[d][t];
        if (d == 0) {
#pragma unroll 16
            for (int t = 0; t < 64; t++) { float v = qs[c][t]; accq += v*v; }
        }
        if (c == 0) {
#pragma unroll 16
            for (int t = 0; t < 64; t++) { float v = ks[d][t]; acck += v*v; }
        }
    }
    g_Spart[(((long)sp*Bn + b)*HEADSn + h)*1024 + tid] = acc;
    if (d == 0) g_nqpart[((long)sp*Bn + b)*Cc + h*HDn + c] = accq;
    if (c == 0) g_nkpart[((long)sp*Bn + b)*Cc + h*HDn + d] = acck;
}

// ------------------------- mask generator + softmax --------------------------
__global__ void k_masksm(const float* __restrict__ fp_w,  const float* __restrict__ fp_b,
                         const float* __restrict__ mg1_w, const float* __restrict__ mg1_b,
                         const float* __restrict__ mg2_w, const float* __restrict__ mg2_b,
                         const float* __restrict__ temp)
{
    int h = blockIdx.x, b = blockIdx.y;
    int t = threadIdx.x;
    __shared__ float comb[64], fin[256], h1[128];
    if (t < 32)           comb[t] = g_opm[b*Cc + h*HDn + t];
    else if (t < 64)      comb[t] = g_spm[b*Cc + h*HDn + (t-32)];
    if (t >= 128 && t < 256) fin[t] = g_pp[b*MHn + (t-128)];
    __syncthreads();
    if (t < 128) {
        float a = fp_b[t];
#pragma unroll 8
        for (int i = 0; i < 64; i++) a += comb[i]*fp_w[t*64 + i];
        fin[t] = a;
    }
    __syncthreads();
    if (t < 128) {
        float a = mg1_b[t];
        for (int i = 0; i < 256; i++) a += fin[i]*mg1_w[t*256 + i];
        h1[t] = fmaxf(a, 0.f);
    }
    __syncthreads();
    float a = mg2_b[t];
    for (int i = 0; i < 128; i++) a += h1[i]*mg2_w[t*128 + i];
    float mg = 1.f / (1.f + expf(-a));

    int c = t >> 5, d = t & 31;
    float s = 0.f, nq = 0.f, nk = 0.f;
#pragma unroll
    for (int sp = 0; sp < NSPLIT; sp++) {
        s  += g_Spart[(((long)sp*Bn + b)*HEADSn + h)*1024 + t];
        nq += g_nqpart[((long)sp*Bn + b)*Cc + h*HDn + c];
        nk += g_nkpart[((long)sp*Bn + b)*Cc + h*HDn + d];
    }
    float val = s / (fmaxf(sqrtf(nq), 1e-12f) * fmaxf(sqrtf(nk), 1e-12f));
    val = val * temp[h] * mg;
    float m = val;
    for (int o = 16; o > 0; o >>= 1) m = fmaxf(m, __shfl_xor_sync(0xffffffffu, m, o));
    float e = expf(val - m);
    float ssum = e;
    for (int o = 16; o > 0; o >>= 1) ssum += __shfl_xor_sync(0xffffffffu, ssum, o);
    g_probs[((long)b*HEADSn + h)*1024 + t] = e / ssum;
}

// ------------------------- M = o_w · blockdiag(probs) -----------------------
__global__ void k_M(const float* __restrict__ o_w)
{
    int b = blockIdx.x, o = blockIdx.y;
    int col = threadIdx.x;
    __shared__ float ow[256];
    __shared__ float pr[HEADSn*HDn*HDn];
    ow[col] = o_w[o*Cc + col];
    for (int i = col; i < HEADSn*HDn*HDn; i += 256) pr[i] = g_probs[(long)b*HEADSn*HDn*HDn + i];
    __syncthreads();
    int h = col >> 5, d = col & 31;
    float a = 0.f;
#pragma unroll 8
    for (int c = 0; c < 32; c++) a += ow[h*HDn + c] * pr[h*1024 + c*32 + d];
    g_M[((long)b*Cc + o)*Cc + col] = a;
}

// ------------------------- depthwise 3x3 + exact gelu gate ------------------
__global__ __launch_bounds__(256)
void k_dwgelu(const float* __restrict__ tin, const float* __restrict__ dw)
{
    __shared__ float s1[10][36], s2[10][36];
    int zc = blockIdx.z;
    int b  = zc / HIDn;
    int c  = zc % HIDn;
    int x0 = blockIdx.x*32;
    int y0 = blockIdx.y*8;
    const float* p1 = tin + ((long)b*2*HIDn + c)*HWn;
    const float* p2 = p1 + (long)HIDn*HWn;

    for (int i = threadIdx.x; i < 340; i += 256) {
        int ry = i / 34, rx = i % 34;
        int yy = y0 + ry - 1, xx = x0 + rx - 1;
        bool ok = (yy >= 0) && (yy < Hh) && (xx >= 0) && (xx < Ww);
        long off = (long)yy*Ww + xx;
        s1[ry][rx] = ok ? p1[off] : 0.f;
        s2[ry][rx] = ok ? p2[off] : 0.f;
    }
    const float* w1 = dw + c*9;
    const float* w2 = dw + (c + HIDn)*9;
    float c1[9], c2[9];
#pragma unroll
    for (int i = 0; i < 9; i++) { c1[i] = w1[i]; c2[i] = w2[i]; }
    __syncthreads();

    int lx = threadIdx.x & 31, ly = threadIdx.x >> 5;
    float a1 = 0.f, a2 = 0.f;
#pragma unroll
    for (int ky = 0; ky < 3; ky++)
#pragma unroll
        for (int kx = 0; kx < 3; kx++) {
            a1 += s1[ly+ky][lx+kx]*c1[ky*3+kx];
            a2 += s2[ly+ky][lx+kx]*c2[ky*3+kx];
        }
    float g = 0.5f*a1*(1.f + erff(a1*0.70710678118654752f));
    float v = g * a2;
    long idx = ((long)b*HIDn + c)*HWn + (y0+ly)*Ww + (x0+lx);
    __half hh, ll;
    split1h(v, hh, ll);
    g_g16h[idx] = hh;
    g_g16l[idx] = ll;
}

// ------------------------- vector copy (img2 passthrough) -------------------
__global__ void k_copy(const float* __restrict__ src, float* __restrict__ dst, long n4)
{
    long i = (long)blockIdx.x*blockDim.x + threadIdx.x;
    if (i < n4) ((float4*)dst)[i] = ((const float4*)src)[i];
}

// ----------------------------------------------------------------------------
extern "C" void kernel_launch(void* const* d_in, const int* in_sizes, int n_in,
                              void* d_out, int out_size)
{
    const float* img    = (const float*)d_in[0];
    const float* text   = (const float*)d_in[1];
    const float* lin1_w = (const float*)d_in[2];
    const float* lin1_b = (const float*)d_in[3];
    const float* lin3_w = (const float*)d_in[4];
    const float* lin3_b = (const float*)d_in[5];
    const float* c1w    = (const float*)d_in[6];
    const float* c1b    = (const float*)d_in[7];
    const float* cow    = (const float*)d_in[8];
    const float* cob    = (const float*)d_in[9];
    const float* n1w    = (const float*)d_in[10];
    const float* n1b    = (const float*)d_in[11];
    const float* n2w    = (const float*)d_in[12];
    const float* n2b    = (const float*)d_in[13];
    const float* n3w    = (const float*)d_in[14];
    const float* n3b    = (const float*)d_in[15];
    const float* q_w    = (const float*)d_in[16];
    const float* k_w    = (const float*)d_in[17];
    const float* v_w    = (const float*)d_in[18];
    const float* o_w    = (const float*)d_in[19];
    const float* temp   = (const float*)d_in[20];
    const float* fp_w   = (const float*)d_in[21];
    const float* fp_b   = (const float*)d_in[22];
    const float* pp_w   = (const float*)d_in[23];
    const float* pp_b   = (const float*)d_in[24];
    const float* mg1_w  = (const float*)d_in[25];
    const float* mg1_b  = (const float*)d_in[26];
    const float* mg2_w  = (const float*)d_in[27];
    const float* mg2_b  = (const float*)d_in[28];
    const float* pi_w   = (const float*)d_in[29];
    const float* dw_w   = (const float*)d_in[30];
    const float* po_w   = (const float*)d_in[31];
    float* out = (float*)d_out;

    cudaFuncSetAttribute(k_mma,  cudaFuncAttributeMaxDynamicSharedMemorySize, MMA_SMEM);
    cudaFuncSetAttribute(k_mmah, cudaFuncAttributeMaxDynamicSharedMemorySize, MMAH_SMEM);

    float *p_Weff, *p_beff, *p_qn, *p_q, *p_k, *p_att, *p_t, *p_opm, *p_spm, *p_M, *p_Watt;
    float *p_pp, *p_t1v, *p_t2v;
    cudaGetSymbolAddress((void**)&p_Weff, g_Weff);
    cudaGetSymbolAddress((void**)&p_beff, g_beff);
    cudaGetSymbolAddress((void**)&p_qn,   g_qn);
    cudaGetSymbolAddress((void**)&p_q,    g_q);
    cudaGetSymbolAddress((void**)&p_k,    g_k);
    cudaGetSymbolAddress((void**)&p_att,  g_att);
    cudaGetSymbolAddress((void**)&p_t,    g_t);
    cudaGetSymbolAddress((void**)&p_opm,  g_opm);
    cudaGetSymbolAddress((void**)&p_spm,  g_spm);
    cudaGetSymbolAddress((void**)&p_M,    g_M);
    cudaGetSymbolAddress((void**)&p_Watt, g_Watt);
    cudaGetSymbolAddress((void**)&p_pp,   g_pp);
    cudaGetSymbolAddress((void**)&p_t1v,  g_t1v);
    cudaGetSymbolAddress((void**)&p_t2v,  g_t2v);

    __nv_bfloat16 *imgh,*imgl,*qnh,*qnl,*knh,*knl;
    __nv_bfloat16 *weh,*wel,*wah,*wal,*qwh,*qwl,*kwh,*kwl;
    cudaGetSymbolAddress((void**)&imgh, g_img_h); cudaGetSymbolAddress((void**)&imgl, g_img_l);
    cudaGetSymbolAddress((void**)&qnh,  g_qn_h);  cudaGetSymbolAddress((void**)&qnl,  g_qn_l);
    cudaGetSymbolAddress((void**)&knh,  g_kn_h);  cudaGetSymbolAddress((void**)&knl,  g_kn_l);
    cudaGetSymbolAddress((void**)&weh,  g_Weff_h);cudaGetSymbolAddress((void**)&wel,  g_Weff_l);
    cudaGetSymbolAddress((void**)&wah,  g_Watt_h);cudaGetSymbolAddress((void**)&wal,  g_Watt_l);
    cudaGetSymbolAddress((void**)&qwh,  g_qw_h);  cudaGetSymbolAddress((void**)&qwl,  g_qw_l);
    cudaGetSymbolAddress((void**)&kwh,  g_kw_h);  cudaGetSymbolAddress((void**)&kwl,  g_kw_l);

    __half *xlh16,*xll16,*gh16,*gl16,*pi16,*po16;
    cudaGetSymbolAddress((void**)&xlh16, g_xln16h);
    cudaGetSymbolAddress((void**)&xll16, g_xln16l);
    cudaGetSymbolAddress((void**)&gh16,  g_g16h);
    cudaGetSymbolAddress((void**)&gl16,  g_g16l);
    cudaGetSymbolAddress((void**)&pi16,  g_piw16);
    cudaGetSymbolAddress((void**)&po16,  g_pow16);

    // 0. input / static weight splits
    k_split<<<16384, 256>>>(img,  imgh, imgl, NIMG/4);
    k_split<<<64,    256>>>(q_w,  qwh,  qwl,  (long)Cc*Cc/4);
    k_split<<<64,    256>>>(k_w,  kwh,  kwl,  (long)Cc*Cc/4);
    k_splith<<<340,  256>>>(pi_w, pi16, (long)2*HIDn*Cc/4);
    k_splith<<<170,  256>>>(po_w, po16, (long)Cc*HIDn/4);

    // 1. text MLP in exact serial order (rank-safe)
    k_lin<<<dim3(LINn/32, Bn), 32>>>(lin1_w, text,  lin1_b, p_t1v, LINn, LINn);
    k_lin<<<dim3(MHn/32,  Bn), 32>>>(pp_w,   text,  pp_b,   p_pp,  MHn,  LINn);
    k_lin<<<dim3(LINn/32, Bn), 32>>>(lin3_w, p_t1v, lin3_b, p_t2v, LINn, LINn);
    k_rank<<<Bn, LINn>>>(p_t2v);
    // 2. effective shuffle weight/bias
    k_beff<<<Bn, Cc>>>(cow, cob, c1b);
    k_weff<<<dim3(16,16,Bn), dim3(16,16)>>>(cow, c1w);
    k_split<<<256, 256>>>(p_Weff, weh, wel, (long)Bn*Cc*Cc/4);
    // 3. qn_raw = W_eff @ img + b_eff ; LN -> hi/lo splits
    k_mma<<<dim3(128,2,Bn), 256, MMA_SMEM>>>(weh, wel, imgh, imgl, p_qn, p_beff, nullptr,
                                             Cc, Cc, HWn, (long)Cc*Cc, CHW, CHW, Cc, 0);
    k_ln<<<dim3(16,Bn), 256>>>(p_qn, qnh, qnl, n1w, n1b);
    k_ln<<<dim3(16,Bn), 256>>>(img,  knh, knl, n2w, n2b);
    // 4. q = q_w@qn, k = k_w@kn (fp32 out for scores)
    k_mma<<<dim3(128,2,Bn), 256, MMA_SMEM>>>(qwh, qwl, qnh, qnl, p_q, nullptr, nullptr,
                                             Cc, Cc, HWn, 0, CHW, CHW, 0, 0);
    k_mma<<<dim3(128,2,Bn), 256, MMA_SMEM>>>(kwh, kwl, knh, knl, p_k, nullptr, nullptr,
                                             Cc, Cc, HWn, 0, CHW, CHW, 0, 0);
    // 5. channel means
    k_chmean<<<dim3(Cc,Bn), 256>>>(knh, knl, p_opm);
    k_chmean<<<dim3(Cc,Bn), 256>>>(qnh, qnl, p_spm);
    // 6. per-head scores partials + norms
    k_scores<<<dim3(NSPLIT, HEADSn, Bn), dim3(32,32)>>>(p_q, p_k);
    // 7. mask generator + softmax -> probs
    k_masksm<<<dim3(HEADSn, Bn), 1024>>>(fp_w, fp_b, mg1_w, mg1_b, mg2_w, mg2_b, temp);
    // 8. M = o_w · blockdiag(probs);  W_att = M @ v_w
    k_M<<<dim3(Bn, Cc), 256>>>(o_w);
    k_gemm<<<dim3(2,2,Bn), 256>>>(p_M, v_w, p_Watt, Cc, Cc, Cc,
                                  (long)Cc*Cc, 0, (long)Cc*Cc);
    k_split<<<256, 256>>>(p_Watt, wah, wal, (long)Bn*Cc*Cc/4);
    // 9. att = W_att @ kn
    k_mma<<<dim3(128,2,Bn), 256, MMA_SMEM>>>(wah, wal, knh, knl, p_att, nullptr, nullptr,
                                             Cc, Cc, HWn, (long)Cc*Cc, CHW, CHW, 0, 0);
    // 10. FFN (fp16 2-term path)
    k_lnh<<<dim3(16,Bn), 256>>>(p_att, xlh16, xll16, n3w, n3b);
    k_mmah<<<dim3(128,11,Bn), 256, MMAH_SMEM>>>(pi16, xlh16, xll16, p_t, nullptr,
                                                2*HIDn, Cc, HWn, 0, CHW, (long)2*HIDn*HWn, 0);
    k_dwgelu<<<dim3(4,16,Bn*HIDn), 256>>>(p_t, dw_w);
    k_mmah<<<dim3(128,2,Bn), 256, MMAH_SMEM>>>(po16, gh16, gl16, out, p_att,
                                               Cc, HIDn, HWn, 0, (long)HIDn*HWn, CHW, CHW);
    // 11. second tuple output: img2 passthrough
    if ((long)out_size >= 2*NIMG)
        k_copy<<<16384, 256>>>(img, out + NIMG, NIMG/4);
}

// round 17
// speedup vs baseline: 1.1834x; 1.0348x over previous
#include <cuda_runtime.h>
#include <cuda_bf16.h>
#include <cuda_fp16.h>
#include <math.h>
#include <stdint.h>

#define Bn     4
#define Cc     256
#define Hh     128
#define Ww     128
#define HWn    16384
#define HEADSn 8
#define HDn    32
#define LINn   512
#define HIDn   680
#define MHn    128
#define NSPLIT 8

#define CHW    ((long)Cc*HWn)          // 4194304
#define NIMG   ((long)Bn*Cc*HWn)       // 16777216

// ------------------------- scratch (static device memory) -------------------
__device__ int   g_idx [Bn*LINn];
__device__ float g_pp  [Bn*MHn];
__device__ float g_t1v [Bn*LINn];
__device__ float g_t2v [Bn*LINn];
__device__ float g_Weff[Bn*Cc*Cc];
__device__ float g_beff[Bn*Cc];
__device__ float g_qn  [Bn*Cc*HWn];
__device__ float g_q   [Bn*Cc*HWn];
__device__ float g_k   [Bn*Cc*HWn];
__device__ float g_att [Bn*Cc*HWn];
__device__ float g_t   [Bn*2*HIDn*HWn];
__device__ float g_Spart [NSPLIT*Bn*HEADSn*HDn*HDn];
__device__ float g_nqpart[NSPLIT*Bn*Cc];
__device__ float g_nkpart[NSPLIT*Bn*Cc];
__device__ float g_opm [Bn*Cc];
__device__ float g_spm [Bn*Cc];
__device__ float g_probs[Bn*HEADSn*HDn*HDn];
__device__ float g_M   [Bn*Cc*Cc];
__device__ float g_Watt[Bn*Cc*Cc];

// fp16 hi/lo activation buffers
__device__ __half g_img16h[NIMG], g_img16l[NIMG];
__device__ __half g_qn16h [NIMG], g_qn16l [NIMG];
__device__ __half g_kn16h [NIMG], g_kn16l [NIMG];
__device__ __half g_xln16h[NIMG], g_xln16l[NIMG];
__device__ __half g_g16h[(long)Bn*HIDn*HWn], g_g16l[(long)Bn*HIDn*HWn];
// fp16 weights
__device__ __half g_Weff16[Bn*Cc*Cc];
__device__ __half g_Watt16[Bn*Cc*Cc];
__device__ __half g_qw16[Cc*Cc];
__device__ __half g_kw16[Cc*Cc];
__device__ __half g_piw16[2*HIDn*Cc];
__device__ __half g_pow16[Cc*HIDn];

// ------------------------- PTX helpers --------------------------------------
__device__ __forceinline__ uint32_t s2u32(const void* p){
    uint32_t r;
    asm("{.reg .u64 t; cvta.to.shared.u64 t, %1; cvt.u32.u64 %0, t;}"
        : "=r"(r) : "l"(p));
    return r;
}
__device__ __forceinline__ void ldsm_x4(uint32_t* r, uint32_t a){
    asm volatile("ldmatrix.sync.aligned.m8n8.x4.shared.b16 {%0,%1,%2,%3},[%4];"
        : "=r"(r[0]),"=r"(r[1]),"=r"(r[2]),"=r"(r[3]) : "r"(a));
}
__device__ __forceinline__ void ldsm_x4t(uint32_t* r, uint32_t a){
    asm volatile("ldmatrix.sync.aligned.m8n8.x4.trans.shared.b16 {%0,%1,%2,%3},[%4];"
        : "=r"(r[0]),"=r"(r[1]),"=r"(r[2]),"=r"(r[3]) : "r"(a));
}
__device__ __forceinline__ void mma16816h(float* c, const uint32_t* a, const uint32_t* b){
    asm volatile("mma.sync.aligned.m16n8k16.row.col.f32.f16.f16.f32 "
        "{%0,%1,%2,%3},{%4,%5,%6,%7},{%8,%9},{%0,%1,%2,%3};"
        : "+f"(c[0]),"+f"(c[1]),"+f"(c[2]),"+f"(c[3])
        : "r"(a[0]),"r"(a[1]),"r"(a[2]),"r"(a[3]),"r"(b[0]),"r"(b[1]));
}
__device__ __forceinline__ void split1h(float v, __half& h, __half& l){
    h = __float2half_rn(v);
    l = __float2half_rn(v - __half2float(h));
}
__device__ __forceinline__ void cpa16(uint32_t s, const void* g, bool v){
    int sz = v ? 16 : 0;
    asm volatile("cp.async.cg.shared.global [%0], [%1], 16, %2;"
                 :: "r"(s), "l"(g), "r"(sz));
}
#define CP_COMMIT() asm volatile("cp.async.commit_group;")
#define CP_WAIT(n)  asm volatile("cp.async.wait_group %0;" :: "n"(n))

// ------------------------- serial-order linear layers ------------------------
__global__ void k_lin(const float* __restrict__ W, const float* __restrict__ x,
                      const float* __restrict__ bias, float* __restrict__ y,
                      int Odim, int In)
{
    int b = blockIdx.y;
    int o = blockIdx.x*32 + threadIdx.x;
    if (o >= Odim) return;
    const float* xr = x + (long)b*In;
    const float* wr = W + (long)o*In;
    float a = bias[o];
#pragma unroll 8
    for (int i = 0; i < In; i++) a += xr[i]*wr[i];
    y[(long)b*Odim + o] = a;
}

// ------------------------- stable descending rank (== top_k indices) --------
__global__ void k_rank(const float* __restrict__ t2)
{
    int b = blockIdx.x, t = threadIdx.x;
    __shared__ float s[LINn];
    s[t] = t2[b*LINn + t];
    __syncthreads();
    float v = s[t];
    int rank = 0;
    for (int i = 0; i < LINn; i++) {
        float u = s[i];
        rank += (u > v) || (u == v && i < t);
    }
    g_idx[b*LINn + rank] = t;
}

// ------------------------- effective shuffle weight -------------------------
__global__ void k_beff(const float* __restrict__ cow, const float* __restrict__ cob,
                       const float* __restrict__ c1b)
{
    int b = blockIdx.x, o = threadIdx.x;
    float a = cob[o];
    for (int j = 0; j < 2*Cc; j++) a += cow[o*2*Cc + j] * c1b[g_idx[b*LINn + j]];
    g_beff[b*Cc + o] = a;
}

__global__ void k_weff(const float* __restrict__ cow, const float* __restrict__ c1w)
{
    int b = blockIdx.z;
    int o = blockIdx.y*16 + threadIdx.y;
    int i = blockIdx.x*16 + threadIdx.x;
    __shared__ int sidx[2*Cc];
    int t = threadIdx.y*16 + threadIdx.x;
    sidx[t]       = g_idx[b*LINn + t];
    sidx[t + 256] = g_idx[b*LINn + t + 256];
    __syncthreads();
    float a = 0.f;
    for (int j = 0; j < 2*Cc; j++) a += cow[o*2*Cc + j] * c1w[sidx[j]*Cc + i];
    g_Weff[((long)b*Cc + o)*Cc + i] = a;
}

// ------------------------- elementwise fp32 -> (hi,lo) fp16 -----------------
__global__ void k_split2h(const float* __restrict__ s, __half* __restrict__ h,
                          __half* __restrict__ l, long n4)
{
    long i = (long)blockIdx.x*blockDim.x + threadIdx.x;
    if (i >= n4) return;
    float4 v = ((const float4*)s)[i];
    __half h0,h1,h2,h3,l0,l1,l2,l3;
    split1h(v.x,h0,l0); split1h(v.y,h1,l1); split1h(v.z,h2,l2); split1h(v.w,h3,l3);
    ((__half2*)h)[i*2]   = __halves2half2(h0,h1);
    ((__half2*)h)[i*2+1] = __halves2half2(h2,h3);
    ((__half2*)l)[i*2]   = __halves2half2(l0,l1);
    ((__half2*)l)[i*2+1] = __halves2half2(l2,l3);
}

// ------------------------- elementwise fp32 -> single fp16 ------------------
__global__ void k_splith(const float* __restrict__ s, __half* __restrict__ h, long n4)
{
    long i = (long)blockIdx.x*blockDim.x + threadIdx.x;
    if (i >= n4) return;
    float4 v = ((const float4*)s)[i];
    ((__half2*)h)[i*2]   = __floats2half2_rn(v.x, v.y);
    ((__half2*)h)[i*2+1] = __floats2half2_rn(v.z, v.w);
}

// ------------------------- fp16 2-term tensor-core GEMM ---------------------
// C = W @ (Xh + Xl), fp32 accum. W:[M,K] fp16 rm, X hi/lo:[K,N] fp16 rm.
#define WP 40
#define XP 136
#define MMAH_SMEM (2*128*WP*2 + 2*2*32*XP*2)   // 20480 + 34816 = 55296
__global__ __launch_bounds__(256, 2)
void k_mmah(const __half* __restrict__ WG,
            const __half* __restrict__ XhiG, const __half* __restrict__ XloG,
            float* __restrict__ Cg, const float* __restrict__ biasg,
            const float* __restrict__ resg,
            int M, int K, int N, long sW, long sX, long sC, long sB, long sR)
{
    extern __shared__ __align__(16) unsigned char dyn[];
    uint32_t aW = s2u32(dyn);
    uint32_t aX = aW + 20480;

    int bz = blockIdx.z;
    const __half* W  = WG   + (long)bz*sW;
    const __half* Xh = XhiG + (long)bz*sX;
    const __half* Xl = XloG + (long)bz*sX;
    float* C = Cg + (long)bz*sC;
    const float* bias = biasg ? biasg + (long)bz*sB : nullptr;
    const float* res  = resg  ? resg  + (long)bz*sR : nullptr;

    int m0 = blockIdx.y*128, n0 = blockIdx.x*128;
    int tid = threadIdx.x, lane = tid & 31, w = tid >> 5;
    int wr = w >> 2, wc = w & 3;

    int wrow = tid >> 2;
    int wcol = (tid & 3) * 8;
    int xrow = tid >> 4;
    int xcol = (tid & 15) * 8;

    auto issue = [&](int kt, int buf){
        long k0 = (long)kt*32;
#pragma unroll
        for (int p = 0; p < 2; p++) {
            int gm = m0 + wrow + p*64; if (gm >= M) gm = M - 1;
            long kk = k0 + wcol;
            bool vw = (kk + 8 <= (long)K);
            long kwc = vw ? kk : 0;
            uint32_t dW = aW + buf*10240 + (wrow + p*64)*80 + wcol*2;
            cpa16(dW, W + (long)gm*K + kwc, vw);
            long gk = k0 + xrow + p*16;
            bool vx = (gk < (long)K);
            long gkc = vx ? gk : 0;
            uint32_t dX = aX + buf*17408 + (xrow + p*16)*272 + xcol*2;
            cpa16(dX,         Xh + gkc*N + n0 + xcol, vx);
            cpa16(dX + 8704,  Xl + gkc*N + n0 + xcol, vx);
        }
        CP_COMMIT();
    };

    int arow = wr*64 + (lane & 15);
    int acol = (lane >> 4) * 8;
    int brow = ((lane >> 3) & 1)*8 + (lane & 7);
    int bcol = wc*32 + (lane >> 4)*8;

    float acc[4][4][4];
#pragma unroll
    for (int i = 0; i < 4; i++)
#pragma unroll
        for (int j = 0; j < 4; j++)
#pragma unroll
            for (int q = 0; q < 4; q++) acc[i][j][q] = 0.f;

    int nt = (K + 31) >> 5;
    issue(0, 0);
    for (int kt = 0; kt < nt; kt++) {
        int buf = kt & 1;
        if (kt + 1 < nt) { issue(kt + 1, buf ^ 1); CP_WAIT(1); }
        else             { CP_WAIT(0); }
        __syncthreads();
        uint32_t bW  = aW + buf*10240;
        uint32_t bXh = aX + buf*17408, bXl = bXh + 8704;
#pragma unroll
        for (int ks = 0; ks < 32; ks += 16) {
            uint32_t bh[4][2], bl[4][2], tmp[4];
#pragma unroll
            for (int np = 0; np < 2; np++) {
                uint32_t off = (uint32_t)((ks + brow)*272 + (bcol + np*16)*2);
                ldsm_x4t(tmp, bXh + off);
                bh[np*2][0]=tmp[0]; bh[np*2][1]=tmp[1];
                bh[np*2+1][0]=tmp[2]; bh[np*2+1][1]=tmp[3];
                ldsm_x4t(tmp, bXl + off);
                bl[np*2][0]=tmp[0]; bl[np*2][1]=tmp[1];
                bl[np*2+1][0]=tmp[2]; bl[np*2+1][1]=tmp[3];
            }
#pragma unroll
            for (int mt = 0; mt < 4; mt++) {
                uint32_t ah[4];
                uint32_t off = (uint32_t)((arow + mt*16)*80 + (ks + acol)*2);
                ldsm_x4(ah, bW + off);
#pragma unroll
                for (int ntl = 0; ntl < 4; ntl++) {
                    mma16816h(acc[mt][ntl], ah, bh[ntl]);
                    mma16816h(acc[mt][ntl], ah, bl[ntl]);
                }
            }
        }
        __syncthreads();
    }

    int r = lane >> 2, cp = (lane & 3)*2;
#pragma unroll
    for (int mt = 0; mt < 4; mt++) {
        int mA = m0 + wr*64 + mt*16 + r;
        int mB = mA + 8;
#pragma unroll
        for (int ntl = 0; ntl < 4; ntl++) {
            int nn = n0 + wc*32 + ntl*8 + cp;
            if (mA < M) {
                float bv = bias ? bias[mA] : 0.f;
                float2 v = make_float2(acc[mt][ntl][0] + bv, acc[mt][ntl][1] + bv);
                if (res) { v.x += res[(long)mA*N + nn]; v.y += res[(long)mA*N + nn + 1]; }
                *(float2*)(C + (long)mA*N + nn) = v;
            }
            if (mB < M) {
                float bv = bias ? bias[mB] : 0.f;
                float2 v = make_float2(acc[mt][ntl][2] + bv, acc[mt][ntl][3] + bv);
                if (res) { v.x += res[(long)mB*N + nn]; v.y += res[(long)mB*N + nn + 1]; }
                *(float2*)(C + (long)mB*N + nn) = v;
            }
        }
    }
}

// ------------------------- scalar SGEMM (small Watt GEMM only) --------------
__global__ __launch_bounds__(256)
void k_gemm(const float* __restrict__ Wg, const float* __restrict__ Xg,
            float* __restrict__ Cg, int M, int K, int N, long sW, long sX, long sC)
{
    int bz = blockIdx.z;
    const float* W = Wg + (long)bz*sW;
    const float* X = Xg + (long)bz*sX;
    float*       C = Cg + (long)bz*sC;
    int m0 = blockIdx.y*128, n0 = blockIdx.x*128;
    __shared__ float Ws[8][128];
    __shared__ float Xs[8][128];
    int tid = threadIdx.x;
    int tx = tid & 15, ty = tid >> 4;
    float acc[8][8];
#pragma unroll
    for (int i = 0; i < 8; i++)
#pragma unroll
        for (int j = 0; j < 8; j++) acc[i][j] = 0.f;
    int wm = tid >> 1, wk = (tid & 1)*4;
    int xk = tid >> 5, xn = (tid & 31)*4;
    for (int k0 = 0; k0 < K; k0 += 8) {
        float4 wv = *(const float4*)(W + (long)(m0 + wm)*K + k0 + wk);
        Ws[wk+0][wm] = wv.x; Ws[wk+1][wm] = wv.y;
        Ws[wk+2][wm] = wv.z; Ws[wk+3][wm] = wv.w;
        *(float4*)&Xs[xk][xn] = *(const float4*)(X + (long)(k0 + xk)*N + n0 + xn);
        __syncthreads();
#pragma unroll
        for (int k = 0; k < 8; k++) {
            float a[8], bb[8];
#pragma unroll
            for (int i = 0; i < 4; i++) { a[i] = Ws[k][ty*4+i]; a[i+4] = Ws[k][64+ty*4+i]; }
#pragma unroll
            for (int j = 0; j < 4; j++) { bb[j] = Xs[k][tx*4+j]; bb[j+4] = Xs[k][64+tx*4+j]; }
#pragma unroll
            for (int i = 0; i < 8; i++)
#pragma unroll
                for (int j = 0; j < 8; j++) acc[i][j] += a[i]*bb[j];
        }
        __syncthreads();
    }
#pragma unroll
    for (int i = 0; i < 8; i++) {
        int m = m0 + ((i < 4) ? ty*4 + i : 64 + ty*4 + (i-4));
        float* crow = C + (long)m*N + n0;
        *(float4*)(crow + tx*4)      = make_float4(acc[i][0],acc[i][1],acc[i][2],acc[i][3]);
        *(float4*)(crow + 64 + tx*4) = make_float4(acc[i][4],acc[i][5],acc[i][6],acc[i][7]);
    }
}

// ------------------------- channel LayerNorm -> hi/lo fp16 ------------------
__global__ void k_lnh(const float* __restrict__ src,
                      __half* __restrict__ dh, __half* __restrict__ dl,
                      const float* __restrict__ w, const float* __restrict__ bias)
{
    int b = blockIdx.y;
    int p4 = blockIdx.x*blockDim.x + threadIdx.x;
    const float4* s = (const float4*)(src + (long)b*CHW) + p4;
    float4 sum = make_float4(0.f,0.f,0.f,0.f);
    float4 sq  = make_float4(0.f,0.f,0.f,0.f);
    for (int c = 0; c < Cc; c++) {
        float4 x = s[(long)c*(HWn/4)];
        sum.x += x.x; sum.y += x.y; sum.z += x.z; sum.w += x.w;
        sq.x += x.x*x.x; sq.y += x.y*x.y; sq.z += x.z*x.z; sq.w += x.w*x.w;
    }
    const float inv = 1.f/Cc;
    float4 mu = make_float4(sum.x*inv, sum.y*inv, sum.z*inv, sum.w*inv);
    float4 rs;
    rs.x = rsqrtf(sq.x*inv - mu.x*mu.x + 1e-5f);
    rs.y = rsqrtf(sq.y*inv - mu.y*mu.y + 1e-5f);
    rs.z = rsqrtf(sq.z*inv - mu.z*mu.z + 1e-5f);
    rs.w = rsqrtf(sq.w*inv - mu.w*mu.w + 1e-5f);
    long base = (long)b*CHW + (long)p4*4;
    for (int c = 0; c < Cc; c++) {
        float4 x = s[(long)c*(HWn/4)];
        float wc = w[c], bc = bias[c];
        float4 o;
        o.x = (x.x - mu.x)*rs.x*wc + bc;
        o.y = (x.y - mu.y)*rs.y*wc + bc;
        o.z = (x.z - mu.z)*rs.z*wc + bc;
        o.w = (x.w - mu.w)*rs.w*wc + bc;
        __half h0,h1,h2,h3,l0,l1,l2,l3;
        split1h(o.x,h0,l0); split1h(o.y,h1,l1); split1h(o.z,h2,l2); split1h(o.w,h3,l3);
        long idx2 = (base + (long)c*HWn) >> 1;
        ((__half2*)dh)[idx2]   = __halves2half2(h0,h1);
        ((__half2*)dh)[idx2+1] = __halves2half2(h2,h3);
        ((__half2*)dl)[idx2]   = __halves2half2(l0,l1);
        ((__half2*)dl)[idx2+1] = __halves2half2(l2,l3);
    }
}

// ------------------------- per-channel mean over HW (hi/lo fp16 input) ------
__global__ void k_chmeanh(const __half* __restrict__ hi,
                          const __half* __restrict__ lo, float* __restrict__ dst)
{
    int b = blockIdx.y, c = blockIdx.x, t = threadIdx.x;
    const __half2* h2 = (const __half2*)(hi + ((long)b*Cc + c)*HWn);
    const __half2* l2 = (const __half2*)(lo + ((long)b*Cc + c)*HWn);
    float a = 0.f;
    for (int i = t; i < HWn/2; i += 256) {
        __half2 hv = h2[i], lv = l2[i];
        a += __half2float(hv.x) + __half2float(hv.y)
           + __half2float(lv.x) + __half2float(lv.y);
    }
    __shared__ float r[256];
    r[t] = a; __syncthreads();
    for (int o = 128; o > 0; o >>= 1) { if (t < o) r[t] += r[t+o]; __syncthreads(); }
    if (t == 0) dst[b*Cc + c] = r[0] * (1.f/HWn);
}

// ------------------------- per-head QK^T partial + row norms ----------------
__global__ void k_scores(const float* __restrict__ q, const float* __restrict__ k)
{
    int sp = blockIdx.x, h = blockIdx.y, b = blockIdx.z;
    int d = threadIdx.x, c = threadIdx.y;
    int tid = c*32 + d;
    const float* Q  = q + ((long)(b*Cc + h*HDn))*HWn;
    const float* Kp = k + ((long)(b*Cc + h*HDn))*HWn;
    __shared__ float qs[32][65], ks[32][65];
    const int chunk = HWn / NSPLIT;
    int n0 = sp*chunk;
    float acc = 0.f, accq = 0.f, acck = 0.f;
    int lr = tid >> 5;
    int lc = (tid & 31) * 2;
    for (int n = n0; n < n0 + chunk; n += 64) {
        float2 qv = *(const float2*)(Q  + (long)lr*HWn + n + lc);
        float2 kv = *(const float2*)(Kp + (long)lr*HWn + n + lc);
        __syncthreads();
        qs[lr][lc] = qv.x; qs[lr][lc+1] = qv.y;
        ks[lr][lc] = kv.x; ks[lr][lc+1] = kv.y;
        __syncthreads();
#pragma unroll 16
        for (int t = 0; t < 64; t++) acc += qs[c][t]*ks[d][t];
        if (d == 0) {
#pragma unroll 16
            for (int t = 0; t < 64; t++) { float v = qs[c][t]; accq += v*v; }
        }
        if (c == 0) {
#pragma unroll 16
            for (int t = 0; t < 64; t++) { float v = ks[d][t]; acck += v*v; }
        }
    }
    g_Spart[(((long)sp*Bn + b)*HEADSn + h)*1024 + tid] = acc;
    if (d == 0) g_nqpart[((long)sp*Bn + b)*Cc + h*HDn + c] = accq;
    if (c == 0) g_nkpart[((long)sp*Bn + b)*Cc + h*HDn + d] = acck;
}

// ------------------------- mask generator + softmax --------------------------
__global__ void k_masksm(const float* __restrict__ fp_w,  const float* __restrict__ fp_b,
                         const float* __restrict__ mg1_w, const float* __restrict__ mg1_b,
                         const float* __restrict__ mg2_w, const float* __restrict__ mg2_b,
                         const float* __restrict__ temp)
{
    int h = blockIdx.x, b = blockIdx.y;
    int t = threadIdx.x;
    __shared__ float comb[64], fin[256], h1[128];
    if (t < 32)           comb[t] = g_opm[b*Cc + h*HDn + t];
    else if (t < 64)      comb[t] = g_spm[b*Cc + h*HDn + (t-32)];
    if (t >= 128 && t < 256) fin[t] = g_pp[b*MHn + (t-128)];
    __syncthreads();
    if (t < 128) {
        float a = fp_b[t];
#pragma unroll 8
        for (int i = 0; i < 64; i++) a += comb[i]*fp_w[t*64 + i];
        fin[t] = a;
    }
    __syncthreads();
    if (t < 128) {
        float a = mg1_b[t];
        for (int i = 0; i < 256; i++) a += fin[i]*mg1_w[t*256 + i];
        h1[t] = fmaxf(a, 0.f);
    }
    __syncthreads();
    float a = mg2_b[t];
    for (int i = 0; i < 128; i++) a += h1[i]*mg2_w[t*128 + i];
    float mg = 1.f / (1.f + expf(-a));

    int c = t >> 5, d = t & 31;
    float s = 0.f, nq = 0.f, nk = 0.f;
#pragma unroll
    for (int sp = 0; sp < NSPLIT; sp++) {
        s  += g_Spart[(((long)sp*Bn + b)*HEADSn + h)*1024 + t];
        nq += g_nqpart[((long)sp*Bn + b)*Cc + h*HDn + c];
        nk += g_nkpart[((long)sp*Bn + b)*Cc + h*HDn + d];
    }
    float val = s / (fmaxf(sqrtf(nq), 1e-12f) * fmaxf(sqrtf(nk), 1e-12f));
    val = val * temp[h] * mg;
    float m = val;
    for (int o = 16; o > 0; o >>= 1) m = fmaxf(m, __shfl_xor_sync(0xffffffffu, m, o));
    float e = expf(val - m);
    float ssum = e;
    for (int o = 16; o > 0; o >>= 1) ssum += __shfl_xor_sync(0xffffffffu, ssum, o);
    g_probs[((long)b*HEADSn + h)*1024 + t] = e / ssum;
}

// ------------------------- M = o_w · blockdiag(probs) -----------------------
__global__ void k_M(const float* __restrict__ o_w)
{
    int b = blockIdx.x, o = blockIdx.y;
    int col = threadIdx.x;
    __shared__ float ow[256];
    __shared__ float pr[HEADSn*HDn*HDn];
    ow[col] = o_w[o*Cc + col];
    for (int i = col; i < HEADSn*HDn*HDn; i += 256) pr[i] = g_probs[(long)b*HEADSn*HDn*HDn + i];
    __syncthreads();
    int h = col >> 5, d = col & 31;
    float a = 0.f;
#pragma unroll 8
    for (int c = 0; c < 32; c++) a += ow[h*HDn + c] * pr[h*1024 + c*32 + d];
    g_M[((long)b*Cc + o)*Cc + col] = a;
}

// ------------------------- depthwise 3x3 + exact gelu gate ------------------
__global__ __launch_bounds__(256)
void k_dwgelu(const float* __restrict__ tin, const float* __restrict__ dw)
{
    __shared__ float s1[10][36], s2[10][36];
    int zc = blockIdx.z;
    int b  = zc / HIDn;
    int c  = zc % HIDn;
    int x0 = blockIdx.x*32;
    int y0 = blockIdx.y*8;
    const float* p1 = tin + ((long)b*2*HIDn + c)*HWn;
    const float* p2 = p1 + (long)HIDn*HWn;

    for (int i = threadIdx.x; i < 340; i += 256) {
        int ry = i / 34, rx = i % 34;
        int yy = y0 + ry - 1, xx = x0 + rx - 1;
        bool ok = (yy >= 0) && (yy < Hh) && (xx >= 0) && (xx < Ww);
        long off = (long)yy*Ww + xx;
        s1[ry][rx] = ok ? p1[off] : 0.f;
        s2[ry][rx] = ok ? p2[off] : 0.f;
    }
    const float* w1 = dw + c*9;
    const float* w2 = dw + (c + HIDn)*9;
    float c1[9], c2[9];
#pragma unroll
    for (int i = 0; i < 9; i++) { c1[i] = w1[i]; c2[i] = w2[i]; }
    __syncthreads();

    int lx = threadIdx.x & 31, ly = threadIdx.x >> 5;
    float a1 = 0.f, a2 = 0.f;
#pragma unroll
    for (int ky = 0; ky < 3; ky++)
#pragma unroll
        for (int kx = 0; kx < 3; kx++) {
            a1 += s1[ly+ky][lx+kx]*c1[ky*3+kx];
            a2 += s2[ly+ky][lx+kx]*c2[ky*3+kx];
        }
    float g = 0.5f*a1*(1.f + erff(a1*0.70710678118654752f));
    float v = g * a2;
    long idx = ((long)b*HIDn + c)*HWn + (y0+ly)*Ww + (x0+lx);
    __half hh, ll;
    split1h(v, hh, ll);
    g_g16h[idx] = hh;
    g_g16l[idx] = ll;
}

// ------------------------- vector copy (img2 passthrough) -------------------
__global__ void k_copy(const float* __restrict__ src, float* __restrict__ dst, long n4)
{
    long i = (long)blockIdx.x*blockDim.x + threadIdx.x;
    if (i < n4) ((float4*)dst)[i] = ((const float4*)src)[i];
}

// ----------------------------------------------------------------------------
extern "C" void kernel_launch(void* const* d_in, const int* in_sizes, int n_in,
                              void* d_out, int out_size)
{
    const float* img    = (const float*)d_in[0];
    const float* text   = (const float*)d_in[1];
    const float* lin1_w = (const float*)d_in[2];
    const float* lin1_b = (const float*)d_in[3];
    const float* lin3_w = (const float*)d_in[4];
    const float* lin3_b = (const float*)d_in[5];
    const float* c1w    = (const float*)d_in[6];
    const float* c1b    = (const float*)d_in[7];
    const float* cow    = (const float*)d_in[8];
    const float* cob    = (const float*)d_in[9];
    const float* n1w    = (const float*)d_in[10];
    const float* n1b    = (const float*)d_in[11];
    const float* n2w    = (const float*)d_in[12];
    const float* n2b    = (const float*)d_in[13];
    const float* n3w    = (const float*)d_in[14];
    const float* n3b    = (const float*)d_in[15];
    const float* q_w    = (const float*)d_in[16];
    const float* k_w    = (const float*)d_in[17];
    const float* v_w    = (const float*)d_in[18];
    const float* o_w    = (const float*)d_in[19];
    const float* temp   = (const float*)d_in[20];
    const float* fp_w   = (const float*)d_in[21];
    const float* fp_b   = (const float*)d_in[22];
    const float* pp_w   = (const float*)d_in[23];
    const float* pp_b   = (const float*)d_in[24];
    const float* mg1_w  = (const float*)d_in[25];
    const float* mg1_b  = (const float*)d_in[26];
    const float* mg2_w  = (const float*)d_in[27];
    const float* mg2_b  = (const float*)d_in[28];
    const float* pi_w   = (const float*)d_in[29];
    const float* dw_w   = (const float*)d_in[30];
    const float* po_w   = (const float*)d_in[31];
    float* out = (float*)d_out;

    cudaFuncSetAttribute(k_mmah, cudaFuncAttributeMaxDynamicSharedMemorySize, MMAH_SMEM);

    float *p_Weff, *p_beff, *p_qn, *p_q, *p_k, *p_att, *p_t, *p_opm, *p_spm, *p_M, *p_Watt;
    float *p_pp, *p_t1v, *p_t2v;
    cudaGetSymbolAddress((void**)&p_Weff, g_Weff);
    cudaGetSymbolAddress((void**)&p_beff, g_beff);
    cudaGetSymbolAddress((void**)&p_qn,   g_qn);
    cudaGetSymbolAddress((void**)&p_q,    g_q);
    cudaGetSymbolAddress((void**)&p_k,    g_k);
    cudaGetSymbolAddress((void**)&p_att,  g_att);
    cudaGetSymbolAddress((void**)&p_t,    g_t);
    cudaGetSymbolAddress((void**)&p_opm,  g_opm);
    cudaGetSymbolAddress((void**)&p_spm,  g_spm);
    cudaGetSymbolAddress((void**)&p_M,    g_M);
    cudaGetSymbolAddress((void**)&p_Watt, g_Watt);
    cudaGetSymbolAddress((void**)&p_pp,   g_pp);
    cudaGetSymbolAddress((void**)&p_t1v,  g_t1v);
    cudaGetSymbolAddress((void**)&p_t2v,  g_t2v);

    __half *img16h,*img16l,*qn16h,*qn16l,*kn16h,*kn16l,*xlh16,*xll16,*gh16,*gl16;
    __half *we16,*wa16,*qw16,*kw16,*pi16,*po16;
    cudaGetSymbolAddress((void**)&img16h, g_img16h);
    cudaGetSymbolAddress((void**)&img16l, g_img16l);
    cudaGetSymbolAddress((void**)&qn16h,  g_qn16h);
    cudaGetSymbolAddress((void**)&qn16l,  g_qn16l);
    cudaGetSymbolAddress((void**)&kn16h,  g_kn16h);
    cudaGetSymbolAddress((void**)&kn16l,  g_kn16l);
    cudaGetSymbolAddress((void**)&xlh16,  g_xln16h);
    cudaGetSymbolAddress((void**)&xll16,  g_xln16l);
    cudaGetSymbolAddress((void**)&gh16,   g_g16h);
    cudaGetSymbolAddress((void**)&gl16,   g_g16l);
    cudaGetSymbolAddress((void**)&we16,   g_Weff16);
    cudaGetSymbolAddress((void**)&wa16,   g_Watt16);
    cudaGetSymbolAddress((void**)&qw16,   g_qw16);
    cudaGetSymbolAddress((void**)&kw16,   g_kw16);
    cudaGetSymbolAddress((void**)&pi16,   g_piw16);
    cudaGetSymbolAddress((void**)&po16,   g_pow16);

    // 0. input / static weight splits
    k_split2h<<<16384, 256>>>(img, img16h, img16l, NIMG/4);
    k_splith<<<64,   256>>>(q_w,  qw16, (long)Cc*Cc/4);
    k_splith<<<64,   256>>>(k_w,  kw16, (long)Cc*Cc/4);
    k_splith<<<340,  256>>>(pi_w, pi16, (long)2*HIDn*Cc/4);
    k_splith<<<170,  256>>>(po_w, po16, (long)Cc*HIDn/4);

    // 1. text MLP in exact serial order (rank-safe)
    k_lin<<<dim3(LINn/32, Bn), 32>>>(lin1_w, text,  lin1_b, p_t1v, LINn, LINn);
    k_lin<<<dim3(MHn/32,  Bn), 32>>>(pp_w,   text,  pp_b,   p_pp,  MHn,  LINn);
    k_lin<<<dim3(LINn/32, Bn), 32>>>(lin3_w, p_t1v, lin3_b, p_t2v, LINn, LINn);
    k_rank<<<Bn, LINn>>>(p_t2v);
    // 2. effective shuffle weight/bias
    k_beff<<<Bn, Cc>>>(cow, cob, c1b);
    k_weff<<<dim3(16,16,Bn), dim3(16,16)>>>(cow, c1w);
    k_splith<<<256, 256>>>(p_Weff, we16, (long)Bn*Cc*Cc/4);
    // 3. qn_raw = W_eff @ img + b_eff ; LN -> fp16 hi/lo
    k_mmah<<<dim3(128,2,Bn), 256, MMAH_SMEM>>>(we16, img16h, img16l, p_qn, p_beff, nullptr,
                                               Cc, Cc, HWn, (long)Cc*Cc, CHW, CHW, Cc, 0);
    k_lnh<<<dim3(16,Bn), 256>>>(p_qn, qn16h, qn16l, n1w, n1b);
    k_lnh<<<dim3(16,Bn), 256>>>(img,  kn16h, kn16l, n2w, n2b);
    // 4. q = q_w@qn, k = k_w@kn (fp32 out for scores)
    k_mmah<<<dim3(128,2,Bn), 256, MMAH_SMEM>>>(qw16, qn16h, qn16l, p_q, nullptr, nullptr,
                                               Cc, Cc, HWn, 0, CHW, CHW, 0, 0);
    k_mmah<<<dim3(128,2,Bn), 256, MMAH_SMEM>>>(kw16, kn16h, kn16l, p_k, nullptr, nullptr,
                                               Cc, Cc, HWn, 0, CHW, CHW, 0, 0);
    // 5. channel means
    k_chmeanh<<<dim3(Cc,Bn), 256>>>(kn16h, kn16l, p_opm);
    k_chmeanh<<<dim3(Cc,Bn), 256>>>(qn16h, qn16l, p_spm);
    // 6. per-head scores partials + norms
    k_scores<<<dim3(NSPLIT, HEADSn, Bn), dim3(32,32)>>>(p_q, p_k);
    // 7. mask generator + softmax -> probs
    k_masksm<<<dim3(HEADSn, Bn), 1024>>>(fp_w, fp_b, mg1_w, mg1_b, mg2_w, mg2_b, temp);
    // 8. M = o_w · blockdiag(probs);  W_att = M @ v_w (fp32 scalar GEMM)
    k_M<<<dim3(Bn, Cc), 256>>>(o_w);
    k_gemm<<<dim3(2,2,Bn), 256>>>(p_M, v_w, p_Watt, Cc, Cc, Cc,
                                  (long)Cc*Cc, 0, (long)Cc*Cc);
    k_splith<<<256, 256>>>(p_Watt, wa16, (long)Bn*Cc*Cc/4);
    // 9. att = W_att @ kn
    k_mmah<<<dim3(128,2,Bn), 256, MMAH_SMEM>>>(wa16, kn16h, kn16l, p_att, nullptr, nullptr,
                                               Cc, Cc, HWn, (long)Cc*Cc, CHW, CHW, 0, 0);
    // 10. FFN (fp16 2-term path)
    k_lnh<<<dim3(16,Bn), 256>>>(p_att, xlh16, xll16, n3w, n3b);
    k_mmah<<<dim3(128,11,Bn), 256, MMAH_SMEM>>>(pi16, xlh16, xll16, p_t, nullptr, nullptr,
                                                2*HIDn, Cc, HWn, 0, CHW, (long)2*HIDn*HWn, 0, 0);
    k_dwgelu<<<dim3(4,16,Bn*HIDn), 256>>>(p_t, dw_w);
    k_mmah<<<dim3(128,2,Bn), 256, MMAH_SMEM>>>(po16, gh16, gl16, out, nullptr, p_att,
                                               Cc, HIDn, HWn, 0, (long)HIDn*HWn, CHW, 0, CHW);
    // 11. second tuple output: img2 passthrough
    if ((long)out_size >= 2*NIMG)
        k_copy<<<16384, 256>>>(img, out + NIMG, NIMG/4);
}